// round 1
// baseline (speedup 1.0000x reference)
#include <cuda_runtime.h>
#include <math.h>

#define B_ 8192
#define D_ 1024
#define H_ 1024
#define K_ 100

// Scratch (device globals: no allocation allowed in kernel_launch)
__device__ float g_h1[(size_t)B_ * H_];
__device__ float g_h2[(size_t)B_ * H_];
__device__ float g_logits[(size_t)B_ * K_];

// ---------------- f32x2 packed-FMA helpers (FFMA2 on sm_103a) ----------------
__device__ __forceinline__ unsigned long long pack2(float lo, float hi) {
    unsigned long long r;
    unsigned int l = __float_as_uint(lo), h = __float_as_uint(hi);
    asm("mov.b64 %0, {%1, %2};" : "=l"(r) : "r"(l), "r"(h));
    return r;
}
__device__ __forceinline__ unsigned long long fma2(unsigned long long a,
                                                   unsigned long long b,
                                                   unsigned long long c) {
    unsigned long long d;
    asm("fma.rn.f32x2 %0, %1, %2, %3;" : "=l"(d) : "l"(a), "l"(b), "l"(c));
    return d;
}
__device__ __forceinline__ float2 unpack2(unsigned long long v) {
    unsigned int l, h;
    asm("mov.b64 {%0, %1}, %2;" : "=r"(l), "=r"(h) : "l"(v));
    return make_float2(__uint_as_float(l), __uint_as_float(h));
}

// ---------------- block reduction ----------------
__device__ __forceinline__ float warpSum(float v) {
#pragma unroll
    for (int o = 16; o > 0; o >>= 1) v += __shfl_down_sync(0xffffffffu, v, o);
    return v;
}
__device__ __forceinline__ float blockSum(float v, float* sm, int nwarps) {
    int lane = threadIdx.x & 31, w = threadIdx.x >> 5;
    v = warpSum(v);
    __syncthreads();             // protect sm reuse across calls
    if (lane == 0) sm[w] = v;
    __syncthreads();
    if (w == 0) {
        float x = (lane < nwarps) ? sm[lane] : 0.f;
        x = warpSum(x);
        if (lane == 0) sm[0] = x;
    }
    __syncthreads();
    return sm[0];
}

// ---------------- SGEMM: C = act(A @ B + bias), fp32, FFMA2 inner loop ----------------
// A [M,K] row-major, B [K,N] row-major, C [M,N]. BM=BN=128, BK=8, 256 thr, 8x8 micro.
#define BM 128
#define BN 128
#define BKK 8

__global__ __launch_bounds__(256, 2)
void sgemm_bias_act(const float* __restrict__ A, const float* __restrict__ Bg,
                    const float* __restrict__ bias, float* __restrict__ C,
                    int M, int N, int K, int doSilu)
{
    __shared__ float As[2][BKK][BM];
    __shared__ float Bs[2][BKK][BN];

    const int tid = threadIdx.x;
    const int cx = tid & 15;      // column group 0..15
    const int ry = tid >> 4;      // row group 0..15
    const int c4 = cx * 4;        // thread cols: [c4..c4+3] and [c4+64..c4+67]
    const int r8 = ry * 8;        // thread rows: r8..r8+7

    const int arow = tid >> 1;
    const int acol = (tid & 1) * 4;
    const int brow = tid >> 5;
    const int bcol = (tid & 31) * 4;

    const int gbcol = blockIdx.x * BN + bcol;
    const float* Aptr = A + (size_t)(blockIdx.y * BM + arow) * K + acol;

    unsigned long long acc[8][4];
#pragma unroll
    for (int i = 0; i < 8; i++)
#pragma unroll
        for (int p = 0; p < 4; p++) acc[i][p] = 0ull;

    // load tile 0
    {
        float4 av = *(const float4*)Aptr;
        As[0][acol + 0][arow] = av.x; As[0][acol + 1][arow] = av.y;
        As[0][acol + 2][arow] = av.z; As[0][acol + 3][arow] = av.w;
        const float* bp = Bg + (size_t)brow * N + gbcol;
        float4 bv;
        if (gbcol + 3 < N) {
            bv = *(const float4*)bp;
        } else {
            bv.x = (gbcol + 0 < N) ? bp[0] : 0.f;
            bv.y = (gbcol + 1 < N) ? bp[1] : 0.f;
            bv.z = (gbcol + 2 < N) ? bp[2] : 0.f;
            bv.w = (gbcol + 3 < N) ? bp[3] : 0.f;
        }
        *(float4*)&Bs[0][brow][bcol] = bv;
    }
    __syncthreads();

    const int nt = K / BKK;
    int cur = 0;
    for (int t = 0; t < nt; ++t) {
        float4 pav, pbv;
        if (t + 1 < nt) {
            pav = *(const float4*)(Aptr + (t + 1) * BKK);
            const float* bp = Bg + (size_t)((t + 1) * BKK + brow) * N + gbcol;
            if (gbcol + 3 < N) {
                pbv = *(const float4*)bp;
            } else {
                pbv.x = (gbcol + 0 < N) ? bp[0] : 0.f;
                pbv.y = (gbcol + 1 < N) ? bp[1] : 0.f;
                pbv.z = (gbcol + 2 < N) ? bp[2] : 0.f;
                pbv.w = (gbcol + 3 < N) ? bp[3] : 0.f;
            }
        }
#pragma unroll
        for (int kk = 0; kk < BKK; ++kk) {
            float4 a0 = *(const float4*)&As[cur][kk][r8];
            float4 a1 = *(const float4*)&As[cur][kk][r8 + 4];
            float4 bA = *(const float4*)&Bs[cur][kk][c4];
            float4 bB = *(const float4*)&Bs[cur][kk][c4 + 64];
            unsigned long long b0 = pack2(bA.x, bA.y), b1 = pack2(bA.z, bA.w);
            unsigned long long b2 = pack2(bB.x, bB.y), b3 = pack2(bB.z, bB.w);
            float av[8] = {a0.x, a0.y, a0.z, a0.w, a1.x, a1.y, a1.z, a1.w};
#pragma unroll
            for (int i = 0; i < 8; i++) {
                unsigned long long ad = pack2(av[i], av[i]);
                acc[i][0] = fma2(ad, b0, acc[i][0]);
                acc[i][1] = fma2(ad, b1, acc[i][1]);
                acc[i][2] = fma2(ad, b2, acc[i][2]);
                acc[i][3] = fma2(ad, b3, acc[i][3]);
            }
        }
        if (t + 1 < nt) {
            int nb = cur ^ 1;
            As[nb][acol + 0][arow] = pav.x; As[nb][acol + 1][arow] = pav.y;
            As[nb][acol + 2][arow] = pav.z; As[nb][acol + 3][arow] = pav.w;
            *(float4*)&Bs[nb][brow][bcol] = pbv;
        }
        __syncthreads();
        cur ^= 1;
    }

    // epilogue: bias + optional silu
    const int rowBase = blockIdx.y * BM + r8;
    const int colBase = blockIdx.x * BN;
#pragma unroll
    for (int i = 0; i < 8; i++) {
        int row = rowBase + i;
#pragma unroll
        for (int p = 0; p < 4; p++) {
            float2 v = unpack2(acc[i][p]);
            int col0 = colBase + ((p < 2) ? (c4 + p * 2) : (64 + c4 + (p - 2) * 2));
#pragma unroll
            for (int q = 0; q < 2; q++) {
                int col = col0 + q;
                if (col < N) {
                    float val = ((q == 0) ? v.x : v.y) + bias[col];
                    if (doSilu) val = val / (1.0f + __expf(-val));
                    C[(size_t)row * N + col] = val;
                }
            }
        }
    }
}

// ---------------- LayerNorm (in place), one block per row, 256 threads ----------------
__global__ void layernorm_kernel(float* __restrict__ h, const float* __restrict__ g,
                                 const float* __restrict__ beta)
{
    __shared__ float sred[8];
    int row = blockIdx.x;
    float* r = h + (size_t)row * H_;
    float4 v = ((const float4*)r)[threadIdx.x];
    float s = v.x + v.y + v.z + v.w;
    s = blockSum(s, sred, 8);
    float mu = s * (1.0f / H_);
    float dx = v.x - mu, dy = v.y - mu, dz = v.z - mu, dw = v.w - mu;
    float q = dx * dx + dy * dy + dz * dz + dw * dw;
    q = blockSum(q, sred, 8);
    float rsig = rsqrtf(q * (1.0f / H_) + 1e-5f);
    int c = threadIdx.x * 4;
    float4 o;
    o.x = dx * rsig * g[c + 0] + beta[c + 0];
    o.y = dy * rsig * g[c + 1] + beta[c + 1];
    o.z = dz * rsig * g[c + 2] + beta[c + 2];
    o.w = dw * rsig * g[c + 3] + beta[c + 3];
    ((float4*)r)[threadIdx.x] = o;
}

// ---------------- evidential head ----------------
__device__ __forceinline__ float softplusf(float x) {
    return fmaxf(x, 0.f) + log1pf(__expf(-fabsf(x)));
}
// digamma for x >= 1: shift to >= 6 then asymptotic series (err < 1e-8)
__device__ __forceinline__ float digammaf_(float x) {
    float r = 0.f;
#pragma unroll
    for (int i = 0; i < 5; i++) {
        if (x < 6.f) { r -= __fdividef(1.f, x); x += 1.f; }
    }
    float inv = __fdividef(1.f, x);
    float inv2 = inv * inv;
    float ser = inv2 * (0.0833333333f - inv2 * (0.0083333333f - inv2 * 0.0039682540f));
    return r + logf(x) - 0.5f * inv - ser;
}

__global__ void head_kernel(const float* __restrict__ logits,
                            float* __restrict__ alpha_o, float* __restrict__ evid_o,
                            float* __restrict__ eprob_o, float* __restrict__ vac_o,
                            float* __restrict__ diss_o, float* __restrict__ alea_o)
{
    __shared__ float sb[K_];
    __shared__ float sa[K_];
    __shared__ float sm[4];
    int row = blockIdx.x;
    int t = threadIdx.x;

    float e = 0.f, a = 0.f;
    if (t < K_) {
        float xv = logits[(size_t)row * K_ + t];
        e = softplusf(xv);
        a = e + 1.f;
    }
    float S = blockSum(a, sm, 4);

    if (t < K_) {
        size_t o = (size_t)row * K_ + t;
        alpha_o[o] = a;
        evid_o[o] = e;
        eprob_o[o] = a / S;
        sb[t] = e / S;
        sa[t] = a;
    }
    if (t == 0) vac_o[row] = (float)K_ / S;
    __syncthreads();

    float b2 = (t < K_) ? sb[t] * sb[t] : 0.f;
    float sumb2 = blockSum(b2, sm, 4);

    float full = 0.f;
    for (int idx = t; idx < K_ * K_; idx += 128) {
        int i = idx / K_;
        int j = idx - i * K_;
        float bi = sb[i], bj = sb[j];
        float den = bi + bj + 1e-8f;
        full += (1.f - __fdividef(fabsf(bi - bj), den)) * bi * bj;
    }
    full = blockSum(full, sm, 4);

    float psiS = digammaf_(S);
    float al = 0.f;
    if (t < K_) al = (sa[t] / S) * (digammaf_(sa[t]) - psiS);
    float alea = blockSum(al, sm, 4);

    if (t == 0) {
        diss_o[row] = 0.5f * (full - sumb2);
        alea_o[row] = -alea;
    }
}

// ---------------- launch ----------------
extern "C" void kernel_launch(void* const* d_in, const int* in_sizes, int n_in,
                              void* d_out, int out_size)
{
    const float* x    = (const float*)d_in[0];
    const float* W1   = (const float*)d_in[1];
    const float* b1   = (const float*)d_in[2];
    const float* g    = (const float*)d_in[3];
    const float* beta = (const float*)d_in[4];
    const float* W2   = (const float*)d_in[5];
    const float* b2   = (const float*)d_in[6];
    const float* W3   = (const float*)d_in[7];
    const float* b3   = (const float*)d_in[8];

    float *h1, *h2, *lg;
    cudaGetSymbolAddress((void**)&h1, g_h1);
    cudaGetSymbolAddress((void**)&h2, g_h2);
    cudaGetSymbolAddress((void**)&lg, g_logits);

    dim3 blk(256);
    dim3 g12(H_ / BN, B_ / BM);                 // (8, 64)
    dim3 g3((K_ + BN - 1) / BN, B_ / BM);       // (1, 64)

    sgemm_bias_act<<<g12, blk>>>(x,  W1, b1, h1, B_, H_, D_, 1);
    layernorm_kernel<<<B_, 256>>>(h1, g, beta);
    sgemm_bias_act<<<g12, blk>>>(h1, W2, b2, h2, B_, H_, H_, 1);
    sgemm_bias_act<<<g3,  blk>>>(h2, W3, b3, lg, B_, K_, H_, 0);

    float* out = (float*)d_out;
    const size_t BK = (size_t)B_ * K_;
    head_kernel<<<B_, 128>>>(lg,
                             out,               // alpha
                             out + BK,          // evidence
                             out + 2 * BK,      // expected_prob
                             out + 3 * BK,      // vacuity
                             out + 3 * BK + B_, // dissonance
                             out + 3 * BK + 2 * B_); // aleatoric
}

// round 4
// speedup vs baseline: 1.6951x; 1.6951x over previous
#include <cuda_runtime.h>
#include <cuda_bf16.h>
#include <stdint.h>
#include <math.h>

#define B_ 8192
#define D_ 1024
#define H_ 1024
#define K_ 100
#define KGLOB 1024

// ---------------- device scratch ----------------
__device__ uint4  g_xhi [(size_t)B_ * H_ * 2 / 16];
__device__ uint4  g_xlo [(size_t)B_ * H_ * 2 / 16];
__device__ uint4  g_h1hi[(size_t)B_ * H_ * 2 / 16];
__device__ uint4  g_h1lo[(size_t)B_ * H_ * 2 / 16];
__device__ uint4  g_h2hi[(size_t)B_ * H_ * 2 / 16];
__device__ uint4  g_h2lo[(size_t)B_ * H_ * 2 / 16];
__device__ uint4  g_w1hi[(size_t)H_ * KGLOB * 2 / 16];
__device__ uint4  g_w1lo[(size_t)H_ * KGLOB * 2 / 16];
__device__ uint4  g_w2hi[(size_t)H_ * KGLOB * 2 / 16];
__device__ uint4  g_w2lo[(size_t)H_ * KGLOB * 2 / 16];
__device__ uint4  g_w3hi[(size_t)128 * KGLOB * 2 / 16];
__device__ uint4  g_w3lo[(size_t)128 * KGLOB * 2 / 16];
__device__ float4 g_h1  [(size_t)B_ * H_ / 4];
__device__ float4 g_h2  [(size_t)B_ * H_ / 4];
__device__ float4 g_lg  [(size_t)B_ * K_ / 4];

// ---------------- helpers ----------------
__device__ __forceinline__ uint32_t smem_u32(const void* p) {
    uint32_t a;
    asm("{ .reg .u64 t; cvta.to.shared.u64 t, %1; cvt.u32.u64 %0, t; }" : "=r"(a) : "l"(p));
    return a;
}
__device__ __forceinline__ void cp16(uint32_t dst, const void* src) {
    asm volatile("cp.async.cg.shared.global [%0], [%1], 16;" :: "r"(dst), "l"(src));
}
__device__ __forceinline__ void ldsm4(uint32_t* r, uint32_t a) {
    asm volatile("ldmatrix.sync.aligned.m8n8.x4.shared.b16 {%0,%1,%2,%3}, [%4];"
                 : "=r"(r[0]), "=r"(r[1]), "=r"(r[2]), "=r"(r[3]) : "r"(a));
}
__device__ __forceinline__ void mma_bf16(float* c, const uint32_t* a, const uint32_t* b) {
    asm volatile("mma.sync.aligned.m16n8k16.row.col.f32.bf16.bf16.f32 "
                 "{%0,%1,%2,%3},{%4,%5,%6,%7},{%8,%9},{%0,%1,%2,%3};"
                 : "+f"(c[0]), "+f"(c[1]), "+f"(c[2]), "+f"(c[3])
                 : "r"(a[0]), "r"(a[1]), "r"(a[2]), "r"(a[3]), "r"(b[0]), "r"(b[1]));
}

// smem tile: 128 rows x 32 bf16, row stride 40 bf16 (80B) -> conflict-free ldmatrix
#define TILEB 10240u          // 128 * 80
#define STGB  40960u          // 4 tiles (Ahi,Alo,Bhi,Blo)
#define NSTG  3

__device__ __forceinline__ void issue_stage(
    uint32_t sbase, int stg,
    const __nv_bfloat16* g0, const __nv_bfloat16* g1,
    const __nv_bfloat16* g2, const __nv_bfloat16* g3,
    int kt, int tid)
{
    const int row = tid >> 1;
    const uint32_t db = sbase + (uint32_t)stg * STGB + (uint32_t)row * 80u + (uint32_t)(tid & 1) * 32u;
    const size_t go = (size_t)row * KGLOB + (size_t)kt * 32 + (size_t)(tid & 1) * 16;
    cp16(db + 0u * TILEB,       g0 + go);
    cp16(db + 0u * TILEB + 16u, g0 + go + 8);
    cp16(db + 1u * TILEB,       g1 + go);
    cp16(db + 1u * TILEB + 16u, g1 + go + 8);
    cp16(db + 2u * TILEB,       g2 + go);
    cp16(db + 2u * TILEB + 16u, g2 + go + 8);
    cp16(db + 3u * TILEB,       g3 + go);
    cp16(db + 3u * TILEB + 16u, g3 + go + 8);
    asm volatile("cp.async.commit_group;" ::: "memory");
}

// ---------------- tensor-core GEMM: C[M,Nout] = act(A @ B^T + bias) ----------------
// A hi/lo [M,1024] bf16 row-major; B hi/lo [Npad,1024] bf16 (pre-transposed weights).
// CTA 128x128, BK=32, 8 warps each 64x32. 3-term split: AhiBhi + AhiBlo + AloBhi.
__global__ __launch_bounds__(256, 1)
void gemm_mma(const __nv_bfloat16* __restrict__ Ahi, const __nv_bfloat16* __restrict__ Alo,
              const __nv_bfloat16* __restrict__ Bhi, const __nv_bfloat16* __restrict__ Blo,
              const float* __restrict__ bias, float* __restrict__ C, int Nout, int doSilu)
{
    extern __shared__ __align__(128) char smraw[];
    const uint32_t sbase = smem_u32(smraw);
    const int tid = threadIdx.x, lane = tid & 31, wid = tid >> 5;
    const int warpRow = wid >> 2, warpCol = wid & 3;
    const int rowA = blockIdx.y * 128, rowB = blockIdx.x * 128;

    const __nv_bfloat16* g0 = Ahi + (size_t)rowA * KGLOB;
    const __nv_bfloat16* g1 = Alo + (size_t)rowA * KGLOB;
    const __nv_bfloat16* g2 = Bhi + (size_t)rowB * KGLOB;
    const __nv_bfloat16* g3 = Blo + (size_t)rowB * KGLOB;

    float acc[4][4][4];
#pragma unroll
    for (int mt = 0; mt < 4; mt++)
#pragma unroll
        for (int nt = 0; nt < 4; nt++)
#pragma unroll
            for (int i = 0; i < 4; i++) acc[mt][nt][i] = 0.f;

    issue_stage(sbase, 0, g0, g1, g2, g3, 0, tid);
    issue_stage(sbase, 1, g0, g1, g2, g3, 1, tid);

    const uint32_t aoff_c = (uint32_t)warpRow * 5120u + (uint32_t)(lane & 15) * 80u
                          + (uint32_t)(lane >> 4) * 16u;
    const uint32_t bn = (uint32_t)((lane & 7) | ((lane >> 4) << 3));
    const uint32_t boff_c = ((uint32_t)warpCol * 32u + bn) * 80u + (uint32_t)((lane >> 3) & 1) * 16u;

    const int NITER = KGLOB / 32;   // 32
#pragma unroll 1
    for (int t = 0; t < NITER; t++) {
        asm volatile("cp.async.wait_group 1;" ::: "memory");
        __syncthreads();
        if (t + 2 < NITER) issue_stage(sbase, (t + 2) % NSTG, g0, g1, g2, g3, t + 2, tid);
        else asm volatile("cp.async.commit_group;" ::: "memory");

        const uint32_t cb = sbase + (uint32_t)(t % NSTG) * STGB;
#pragma unroll
        for (int s = 0; s < 2; s++) {
            uint32_t ah[4][4], al[4][4], bh[4][2], bl[4][2], tmp[4];
            const uint32_t ao = cb + aoff_c + (uint32_t)s * 32u;
#pragma unroll
            for (int mt = 0; mt < 4; mt++) ldsm4(ah[mt], ao + (uint32_t)mt * 1280u);
#pragma unroll
            for (int mt = 0; mt < 4; mt++) ldsm4(al[mt], ao + TILEB + (uint32_t)mt * 1280u);
            const uint32_t bo = cb + 2u * TILEB + boff_c + (uint32_t)s * 32u;
            ldsm4(tmp, bo);
            bh[0][0] = tmp[0]; bh[0][1] = tmp[1]; bh[1][0] = tmp[2]; bh[1][1] = tmp[3];
            ldsm4(tmp, bo + 1280u);
            bh[2][0] = tmp[0]; bh[2][1] = tmp[1]; bh[3][0] = tmp[2]; bh[3][1] = tmp[3];
            ldsm4(tmp, bo + TILEB);
            bl[0][0] = tmp[0]; bl[0][1] = tmp[1]; bl[1][0] = tmp[2]; bl[1][1] = tmp[3];
            ldsm4(tmp, bo + TILEB + 1280u);
            bl[2][0] = tmp[0]; bl[2][1] = tmp[1]; bl[3][0] = tmp[2]; bl[3][1] = tmp[3];
#pragma unroll
            for (int mt = 0; mt < 4; mt++)
#pragma unroll
                for (int nt = 0; nt < 4; nt++) {
                    mma_bf16(acc[mt][nt], ah[mt], bh[nt]);
                    mma_bf16(acc[mt][nt], ah[mt], bl[nt]);
                    mma_bf16(acc[mt][nt], al[mt], bh[nt]);
                }
        }
    }

    // epilogue
#pragma unroll
    for (int mt = 0; mt < 4; mt++) {
        const int row0 = rowA + warpRow * 64 + mt * 16 + (lane >> 2);
#pragma unroll
        for (int nt = 0; nt < 4; nt++) {
            const int col = blockIdx.x * 128 + warpCol * 32 + nt * 8 + (lane & 3) * 2;
            if (col < Nout) {
                const float bx = bias[col], by = bias[col + 1];
                float2 v0, v1;
                v0.x = acc[mt][nt][0] + bx; v0.y = acc[mt][nt][1] + by;
                v1.x = acc[mt][nt][2] + bx; v1.y = acc[mt][nt][3] + by;
                if (doSilu) {
                    v0.x = v0.x / (1.f + __expf(-v0.x));
                    v0.y = v0.y / (1.f + __expf(-v0.y));
                    v1.x = v1.x / (1.f + __expf(-v1.x));
                    v1.y = v1.y / (1.f + __expf(-v1.y));
                }
                *(float2*)&C[(size_t)row0 * Nout + col] = v0;
                *(float2*)&C[(size_t)(row0 + 8) * Nout + col] = v1;
            }
        }
    }
}

// ---------------- fp32 -> (hi, lo) bf16 split ----------------
__global__ void split_kernel(const float4* __restrict__ src,
                             __nv_bfloat162* __restrict__ hi, __nv_bfloat162* __restrict__ lo)
{
    const size_t i = (size_t)blockIdx.x * 256 + threadIdx.x;
    float4 v = src[i];
    __nv_bfloat16 h0 = __float2bfloat16(v.x), h1 = __float2bfloat16(v.y);
    __nv_bfloat16 h2 = __float2bfloat16(v.z), h3 = __float2bfloat16(v.w);
    __nv_bfloat16 l0 = __float2bfloat16(v.x - __bfloat162float(h0));
    __nv_bfloat16 l1 = __float2bfloat16(v.y - __bfloat162float(h1));
    __nv_bfloat16 l2 = __float2bfloat16(v.z - __bfloat162float(h2));
    __nv_bfloat16 l3 = __float2bfloat16(v.w - __bfloat162float(h3));
    hi[2 * i]     = __nv_bfloat162(h0, h1);
    hi[2 * i + 1] = __nv_bfloat162(h2, h3);
    lo[2 * i]     = __nv_bfloat162(l0, l1);
    lo[2 * i + 1] = __nv_bfloat162(l2, l3);
}

// ---------------- W [K,N] fp32 -> transposed split [Npad,K] bf16 ----------------
__global__ void transpose_split(const float* __restrict__ W,
                                __nv_bfloat16* __restrict__ Thi, __nv_bfloat16* __restrict__ Tlo,
                                int N)
{
    __shared__ float tile[32][33];
    const int n0 = blockIdx.x * 32, k0 = blockIdx.y * 32;
    const int tx = threadIdx.x, ty = threadIdx.y;
#pragma unroll
    for (int i = 0; i < 4; i++) {
        const int k = k0 + ty + i * 8, n = n0 + tx;
        tile[ty + i * 8][tx] = (n < N) ? W[(size_t)k * N + n] : 0.0f;
    }
    __syncthreads();
#pragma unroll
    for (int i = 0; i < 4; i++) {
        const int n = n0 + ty + i * 8, k = k0 + tx;
        const float v = tile[tx][ty + i * 8];
        const __nv_bfloat16 h = __float2bfloat16(v);
        Thi[(size_t)n * KGLOB + k] = h;
        Tlo[(size_t)n * KGLOB + k] = __float2bfloat16(v - __bfloat162float(h));
    }
}

// ---------------- reductions ----------------
__device__ __forceinline__ float warpSum(float v) {
#pragma unroll
    for (int o = 16; o > 0; o >>= 1) v += __shfl_down_sync(0xffffffffu, v, o);
    return v;
}
__device__ __forceinline__ float blockSum(float v, float* sm, int nwarps) {
    int lane = threadIdx.x & 31, w = threadIdx.x >> 5;
    v = warpSum(v);
    __syncthreads();
    if (lane == 0) sm[w] = v;
    __syncthreads();
    if (w == 0) {
        float x = (lane < nwarps) ? sm[lane] : 0.f;
        x = warpSum(x);
        if (lane == 0) sm[0] = x;
    }
    __syncthreads();
    return sm[0];
}

// ---------------- LayerNorm (in place) ----------------
__global__ void layernorm_kernel(float* __restrict__ h, const float* __restrict__ g,
                                 const float* __restrict__ beta)
{
    __shared__ float sred[8];
    const int row = blockIdx.x;
    float* r = h + (size_t)row * H_;
    float4 v = ((const float4*)r)[threadIdx.x];
    float s = v.x + v.y + v.z + v.w;
    s = blockSum(s, sred, 8);
    const float mu = s * (1.0f / H_);
    const float dx = v.x - mu, dy = v.y - mu, dz = v.z - mu, dw = v.w - mu;
    float q = dx * dx + dy * dy + dz * dz + dw * dw;
    q = blockSum(q, sred, 8);
    const float rsig = rsqrtf(q * (1.0f / H_) + 1e-5f);
    const int c = threadIdx.x * 4;
    float4 o;
    o.x = dx * rsig * g[c + 0] + beta[c + 0];
    o.y = dy * rsig * g[c + 1] + beta[c + 1];
    o.z = dz * rsig * g[c + 2] + beta[c + 2];
    o.w = dw * rsig * g[c + 3] + beta[c + 3];
    ((float4*)r)[threadIdx.x] = o;
}

// ---------------- evidential head ----------------
__device__ __forceinline__ float softplusf(float x) {
    return fmaxf(x, 0.f) + log1pf(__expf(-fabsf(x)));
}
__device__ __forceinline__ float digammaf_(float x) {
    float r = 0.f;
#pragma unroll
    for (int i = 0; i < 5; i++) {
        if (x < 6.f) { r -= __fdividef(1.f, x); x += 1.f; }
    }
    const float inv = __fdividef(1.f, x);
    const float inv2 = inv * inv;
    const float ser = inv2 * (0.0833333333f - inv2 * (0.0083333333f - inv2 * 0.0039682540f));
    return r + logf(x) - 0.5f * inv - ser;
}

__global__ void head_kernel(const float* __restrict__ logits,
                            float* __restrict__ alpha_o, float* __restrict__ evid_o,
                            float* __restrict__ eprob_o, float* __restrict__ vac_o,
                            float* __restrict__ diss_o, float* __restrict__ alea_o)
{
    __shared__ float sb[K_];
    __shared__ float sa[K_];
    __shared__ float sm[4];
    const int row = blockIdx.x;
    const int t = threadIdx.x;

    float e = 0.f, a = 0.f;
    if (t < K_) {
        const float xv = logits[(size_t)row * K_ + t];
        e = softplusf(xv);
        a = e + 1.f;
    }
    const float S = blockSum(a, sm, 4);

    if (t < K_) {
        const size_t o = (size_t)row * K_ + t;
        alpha_o[o] = a;
        evid_o[o] = e;
        eprob_o[o] = a / S;
        sb[t] = e / S;
        sa[t] = a;
    }
    if (t == 0) vac_o[row] = (float)K_ / S;
    __syncthreads();

    const float b2 = (t < K_) ? sb[t] * sb[t] : 0.f;
    const float sumb2 = blockSum(b2, sm, 4);

    float full = 0.f;
    for (int idx = t; idx < K_ * K_; idx += 128) {
        const int i = idx / K_;
        const int j = idx - i * K_;
        const float bi = sb[i], bj = sb[j];
        const float den = bi + bj + 1e-8f;
        full += (1.f - __fdividef(fabsf(bi - bj), den)) * bi * bj;
    }
    full = blockSum(full, sm, 4);

    const float psiS = digammaf_(S);
    float al = 0.f;
    if (t < K_) al = (sa[t] / S) * (digammaf_(sa[t]) - psiS);
    const float alea = blockSum(al, sm, 4);

    if (t == 0) {
        diss_o[row] = 0.5f * (full - sumb2);
        alea_o[row] = -alea;
    }
}

// ---------------- launch ----------------
extern "C" void kernel_launch(void* const* d_in, const int* in_sizes, int n_in,
                              void* d_out, int out_size)
{
    const float* x    = (const float*)d_in[0];
    const float* W1   = (const float*)d_in[1];
    const float* b1   = (const float*)d_in[2];
    const float* g    = (const float*)d_in[3];
    const float* beta = (const float*)d_in[4];
    const float* W2   = (const float*)d_in[5];
    const float* b2   = (const float*)d_in[6];
    const float* W3   = (const float*)d_in[7];
    const float* b3   = (const float*)d_in[8];

    void *p;
    cudaGetSymbolAddress(&p, g_xhi);  __nv_bfloat16* xhi = (__nv_bfloat16*)p;
    cudaGetSymbolAddress(&p, g_xlo);  __nv_bfloat16* xlo = (__nv_bfloat16*)p;
    cudaGetSymbolAddress(&p, g_h1hi); __nv_bfloat16* h1hi = (__nv_bfloat16*)p;
    cudaGetSymbolAddress(&p, g_h1lo); __nv_bfloat16* h1lo = (__nv_bfloat16*)p;
    cudaGetSymbolAddress(&p, g_h2hi); __nv_bfloat16* h2hi = (__nv_bfloat16*)p;
    cudaGetSymbolAddress(&p, g_h2lo); __nv_bfloat16* h2lo = (__nv_bfloat16*)p;
    cudaGetSymbolAddress(&p, g_w1hi); __nv_bfloat16* w1hi = (__nv_bfloat16*)p;
    cudaGetSymbolAddress(&p, g_w1lo); __nv_bfloat16* w1lo = (__nv_bfloat16*)p;
    cudaGetSymbolAddress(&p, g_w2hi); __nv_bfloat16* w2hi = (__nv_bfloat16*)p;
    cudaGetSymbolAddress(&p, g_w2lo); __nv_bfloat16* w2lo = (__nv_bfloat16*)p;
    cudaGetSymbolAddress(&p, g_w3hi); __nv_bfloat16* w3hi = (__nv_bfloat16*)p;
    cudaGetSymbolAddress(&p, g_w3lo); __nv_bfloat16* w3lo = (__nv_bfloat16*)p;
    cudaGetSymbolAddress(&p, g_h1);   float* h1 = (float*)p;
    cudaGetSymbolAddress(&p, g_h2);   float* h2 = (float*)p;
    cudaGetSymbolAddress(&p, g_lg);   float* lg = (float*)p;

    const int DSMEM = NSTG * (int)STGB;   // 122880
    cudaFuncSetAttribute(gemm_mma, cudaFuncAttributeMaxDynamicSharedMemorySize, DSMEM);

    const int splitBlocks = (B_ * H_) / 4 / 256;   // 8192

    // weight prep (transposed + split)
    transpose_split<<<dim3(32, 32), dim3(32, 8)>>>(W1, w1hi, w1lo, H_);
    transpose_split<<<dim3(32, 32), dim3(32, 8)>>>(W2, w2hi, w2lo, H_);
    transpose_split<<<dim3(4, 32),  dim3(32, 8)>>>(W3, w3hi, w3lo, K_);

    // x split
    split_kernel<<<splitBlocks, 256>>>((const float4*)x, (__nv_bfloat162*)xhi, (__nv_bfloat162*)xlo);

    // GEMM1 + silu
    gemm_mma<<<dim3(8, 64), 256, DSMEM>>>(xhi, xlo, w1hi, w1lo, b1, h1, H_, 1);
    // LayerNorm
    layernorm_kernel<<<B_, 256>>>(h1, g, beta);
    // split h1
    split_kernel<<<splitBlocks, 256>>>((const float4*)h1, (__nv_bfloat162*)h1hi, (__nv_bfloat162*)h1lo);
    // GEMM2 + silu
    gemm_mma<<<dim3(8, 64), 256, DSMEM>>>(h1hi, h1lo, w2hi, w2lo, b2, h2, H_, 1);
    // split h2
    split_kernel<<<splitBlocks, 256>>>((const float4*)h2, (__nv_bfloat162*)h2hi, (__nv_bfloat162*)h2lo);
    // GEMM3 (logits, no act). W3 padded to 128 rows; store only 100 cols.
    gemm_mma<<<dim3(1, 64), 256, DSMEM>>>(h2hi, h2lo, w3hi, w3lo, b3, lg, K_, 0);

    float* out = (float*)d_out;
    const size_t BK = (size_t)B_ * K_;
    head_kernel<<<B_, 128>>>(lg,
                             out,                    // alpha
                             out + BK,               // evidence
                             out + 2 * BK,           // expected_prob
                             out + 3 * BK,           // vacuity
                             out + 3 * BK + B_,      // dissonance
                             out + 3 * BK + 2 * B_); // aleatoric
}

// round 5
// speedup vs baseline: 1.9250x; 1.1357x over previous
#include <cuda_runtime.h>
#include <cuda_bf16.h>
#include <stdint.h>
#include <math.h>

#define B_ 8192
#define D_ 1024
#define H_ 1024
#define K_ 100
#define KGLOB 1024

// ---------------- device scratch ----------------
__device__ uint4  g_xhi [(size_t)B_ * H_ * 2 / 16];
__device__ uint4  g_xlo [(size_t)B_ * H_ * 2 / 16];
__device__ uint4  g_h1hi[(size_t)B_ * H_ * 2 / 16];
__device__ uint4  g_h1lo[(size_t)B_ * H_ * 2 / 16];
__device__ uint4  g_h2hi[(size_t)B_ * H_ * 2 / 16];
__device__ uint4  g_h2lo[(size_t)B_ * H_ * 2 / 16];
__device__ uint4  g_w1hi[(size_t)H_ * KGLOB * 2 / 16];
__device__ uint4  g_w1lo[(size_t)H_ * KGLOB * 2 / 16];
__device__ uint4  g_w2hi[(size_t)H_ * KGLOB * 2 / 16];
__device__ uint4  g_w2lo[(size_t)H_ * KGLOB * 2 / 16];
__device__ uint4  g_w3hi[(size_t)128 * KGLOB * 2 / 16];
__device__ uint4  g_w3lo[(size_t)128 * KGLOB * 2 / 16];
__device__ float4 g_h1  [(size_t)B_ * H_ / 4];
__device__ float4 g_lg  [(size_t)B_ * K_ / 4];

// ---------------- helpers ----------------
__device__ __forceinline__ uint32_t smem_u32(const void* p) {
    uint32_t a;
    asm("{ .reg .u64 t; cvta.to.shared.u64 t, %1; cvt.u32.u64 %0, t; }" : "=r"(a) : "l"(p));
    return a;
}
__device__ __forceinline__ void cp16(uint32_t dst, const void* src) {
    asm volatile("cp.async.cg.shared.global [%0], [%1], 16;" :: "r"(dst), "l"(src));
}
__device__ __forceinline__ void ldsm4(uint32_t* r, uint32_t a) {
    asm volatile("ldmatrix.sync.aligned.m8n8.x4.shared.b16 {%0,%1,%2,%3}, [%4];"
                 : "=r"(r[0]), "=r"(r[1]), "=r"(r[2]), "=r"(r[3]) : "r"(a));
}
__device__ __forceinline__ void mma_bf16(float* c, const uint32_t* a, const uint32_t* b) {
    asm volatile("mma.sync.aligned.m16n8k16.row.col.f32.bf16.bf16.f32 "
                 "{%0,%1,%2,%3},{%4,%5,%6,%7},{%8,%9},{%0,%1,%2,%3};"
                 : "+f"(c[0]), "+f"(c[1]), "+f"(c[2]), "+f"(c[3])
                 : "r"(a[0]), "r"(a[1]), "r"(a[2]), "r"(a[3]), "r"(b[0]), "r"(b[1]));
}

// smem tile: 128 rows x 32 bf16, row stride 40 bf16 (80B) -> conflict-free ldmatrix
#define TILEB 10240u          // 128 * 80
#define STGB  40960u          // 4 tiles (Ahi,Alo,Bhi,Blo)
#define NSTG  2

__device__ __forceinline__ void issue_stage(
    uint32_t sbase, int stg,
    const __nv_bfloat16* g0, const __nv_bfloat16* g1,
    const __nv_bfloat16* g2, const __nv_bfloat16* g3,
    int kt, int tid)
{
    const int row = tid >> 1;
    const uint32_t db = sbase + (uint32_t)stg * STGB + (uint32_t)row * 80u + (uint32_t)(tid & 1) * 32u;
    const size_t go = (size_t)row * KGLOB + (size_t)kt * 32 + (size_t)(tid & 1) * 16;
    cp16(db + 0u * TILEB,       g0 + go);
    cp16(db + 0u * TILEB + 16u, g0 + go + 8);
    cp16(db + 1u * TILEB,       g1 + go);
    cp16(db + 1u * TILEB + 16u, g1 + go + 8);
    cp16(db + 2u * TILEB,       g2 + go);
    cp16(db + 2u * TILEB + 16u, g2 + go + 8);
    cp16(db + 3u * TILEB,       g3 + go);
    cp16(db + 3u * TILEB + 16u, g3 + go + 8);
    asm volatile("cp.async.commit_group;" ::: "memory");
}

// ---------------- tensor-core GEMM: out = act(A @ B^T + bias) ----------------
// A hi/lo [M,1024] bf16 row-major; B hi/lo [Npad,1024] bf16 (pre-transposed weights).
// CTA 128x128, BK=32, 8 warps each 64x32. 3-term split: AhiBhi + AhiBlo + AloBhi.
// splitOut=0: write fp32 C.  splitOut=1: write bf16 hi/lo split (Chi/Clo), Nout=1024.
__global__ __launch_bounds__(256, 2)
void gemm_mma(const __nv_bfloat16* __restrict__ Ahi, const __nv_bfloat16* __restrict__ Alo,
              const __nv_bfloat16* __restrict__ Bhi, const __nv_bfloat16* __restrict__ Blo,
              const float* __restrict__ bias, float* __restrict__ C,
              __nv_bfloat16* __restrict__ Chi, __nv_bfloat16* __restrict__ Clo,
              int Nout, int doSilu, int splitOut)
{
    extern __shared__ __align__(128) char smraw[];
    const uint32_t sbase = smem_u32(smraw);
    const int tid = threadIdx.x, lane = tid & 31, wid = tid >> 5;
    const int warpRow = wid >> 2, warpCol = wid & 3;
    const int rowA = blockIdx.y * 128, rowB = blockIdx.x * 128;

    const __nv_bfloat16* g0 = Ahi + (size_t)rowA * KGLOB;
    const __nv_bfloat16* g1 = Alo + (size_t)rowA * KGLOB;
    const __nv_bfloat16* g2 = Bhi + (size_t)rowB * KGLOB;
    const __nv_bfloat16* g3 = Blo + (size_t)rowB * KGLOB;

    float acc[4][4][4];
#pragma unroll
    for (int mt = 0; mt < 4; mt++)
#pragma unroll
        for (int nt = 0; nt < 4; nt++)
#pragma unroll
            for (int i = 0; i < 4; i++) acc[mt][nt][i] = 0.f;

    issue_stage(sbase, 0, g0, g1, g2, g3, 0, tid);

    const uint32_t aoff_c = (uint32_t)warpRow * 5120u + (uint32_t)(lane & 15) * 80u
                          + (uint32_t)(lane >> 4) * 16u;
    const uint32_t bn = (uint32_t)((lane & 7) | ((lane >> 4) << 3));
    const uint32_t boff_c = ((uint32_t)warpCol * 32u + bn) * 80u + (uint32_t)((lane >> 3) & 1) * 16u;

    const int NITER = KGLOB / 32;   // 32
#pragma unroll 1
    for (int t = 0; t < NITER; t++) {
        asm volatile("cp.async.wait_group 0;" ::: "memory");
        __syncthreads();
        if (t + 1 < NITER) issue_stage(sbase, (t + 1) & 1, g0, g1, g2, g3, t + 1, tid);

        const uint32_t cb = sbase + (uint32_t)(t & 1) * STGB;
#pragma unroll
        for (int s = 0; s < 2; s++) {
            uint32_t ah[4][4], al[4][4], bh[4][2], bl[4][2], tmp[4];
            const uint32_t ao = cb + aoff_c + (uint32_t)s * 32u;
#pragma unroll
            for (int mt = 0; mt < 4; mt++) ldsm4(ah[mt], ao + (uint32_t)mt * 1280u);
#pragma unroll
            for (int mt = 0; mt < 4; mt++) ldsm4(al[mt], ao + TILEB + (uint32_t)mt * 1280u);
            const uint32_t bo = cb + 2u * TILEB + boff_c + (uint32_t)s * 32u;
            ldsm4(tmp, bo);
            bh[0][0] = tmp[0]; bh[0][1] = tmp[1]; bh[1][0] = tmp[2]; bh[1][1] = tmp[3];
            ldsm4(tmp, bo + 1280u);
            bh[2][0] = tmp[0]; bh[2][1] = tmp[1]; bh[3][0] = tmp[2]; bh[3][1] = tmp[3];
            ldsm4(tmp, bo + TILEB);
            bl[0][0] = tmp[0]; bl[0][1] = tmp[1]; bl[1][0] = tmp[2]; bl[1][1] = tmp[3];
            ldsm4(tmp, bo + TILEB + 1280u);
            bl[2][0] = tmp[0]; bl[2][1] = tmp[1]; bl[3][0] = tmp[2]; bl[3][1] = tmp[3];
#pragma unroll
            for (int mt = 0; mt < 4; mt++)
#pragma unroll
                for (int nt = 0; nt < 4; nt++) {
                    mma_bf16(acc[mt][nt], ah[mt], bh[nt]);
                    mma_bf16(acc[mt][nt], ah[mt], bl[nt]);
                    mma_bf16(acc[mt][nt], al[mt], bh[nt]);
                }
        }
        __syncthreads();
    }

    // epilogue
#pragma unroll
    for (int mt = 0; mt < 4; mt++) {
        const int row0 = rowA + warpRow * 64 + mt * 16 + (lane >> 2);
#pragma unroll
        for (int nt = 0; nt < 4; nt++) {
            const int col = blockIdx.x * 128 + warpCol * 32 + nt * 8 + (lane & 3) * 2;
            if (col < Nout) {
                const float bx = bias[col], by = bias[col + 1];
                float2 v0, v1;
                v0.x = acc[mt][nt][0] + bx; v0.y = acc[mt][nt][1] + by;
                v1.x = acc[mt][nt][2] + bx; v1.y = acc[mt][nt][3] + by;
                if (doSilu) {
                    v0.x = v0.x / (1.f + __expf(-v0.x));
                    v0.y = v0.y / (1.f + __expf(-v0.y));
                    v1.x = v1.x / (1.f + __expf(-v1.x));
                    v1.y = v1.y / (1.f + __expf(-v1.y));
                }
                if (splitOut) {
                    const size_t o0 = (size_t)row0 * KGLOB + col;
                    const size_t o1 = (size_t)(row0 + 8) * KGLOB + col;
                    __nv_bfloat16 h0x = __float2bfloat16(v0.x), h0y = __float2bfloat16(v0.y);
                    __nv_bfloat16 h1x = __float2bfloat16(v1.x), h1y = __float2bfloat16(v1.y);
                    *(__nv_bfloat162*)(Chi + o0) = __nv_bfloat162(h0x, h0y);
                    *(__nv_bfloat162*)(Chi + o1) = __nv_bfloat162(h1x, h1y);
                    *(__nv_bfloat162*)(Clo + o0) = __nv_bfloat162(
                        __float2bfloat16(v0.x - __bfloat162float(h0x)),
                        __float2bfloat16(v0.y - __bfloat162float(h0y)));
                    *(__nv_bfloat162*)(Clo + o1) = __nv_bfloat162(
                        __float2bfloat16(v1.x - __bfloat162float(h1x)),
                        __float2bfloat16(v1.y - __bfloat162float(h1y)));
                } else {
                    *(float2*)&C[(size_t)row0 * Nout + col] = v0;
                    *(float2*)&C[(size_t)(row0 + 8) * Nout + col] = v1;
                }
            }
        }
    }
}

// ---------------- fp32 -> (hi, lo) bf16 split (input x only) ----------------
__global__ void split_kernel(const float4* __restrict__ src,
                             __nv_bfloat162* __restrict__ hi, __nv_bfloat162* __restrict__ lo)
{
    const size_t i = (size_t)blockIdx.x * 256 + threadIdx.x;
    float4 v = src[i];
    __nv_bfloat16 h0 = __float2bfloat16(v.x), h1 = __float2bfloat16(v.y);
    __nv_bfloat16 h2 = __float2bfloat16(v.z), h3 = __float2bfloat16(v.w);
    hi[2 * i]     = __nv_bfloat162(h0, h1);
    hi[2 * i + 1] = __nv_bfloat162(h2, h3);
    lo[2 * i]     = __nv_bfloat162(__float2bfloat16(v.x - __bfloat162float(h0)),
                                   __float2bfloat16(v.y - __bfloat162float(h1)));
    lo[2 * i + 1] = __nv_bfloat162(__float2bfloat16(v.z - __bfloat162float(h2)),
                                   __float2bfloat16(v.w - __bfloat162float(h3)));
}

// ---------------- W [K,N] fp32 -> transposed split [Npad,K] bf16 ----------------
__global__ void transpose_split(const float* __restrict__ W,
                                __nv_bfloat16* __restrict__ Thi, __nv_bfloat16* __restrict__ Tlo,
                                int N)
{
    __shared__ float tile[32][33];
    const int n0 = blockIdx.x * 32, k0 = blockIdx.y * 32;
    const int tx = threadIdx.x, ty = threadIdx.y;
#pragma unroll
    for (int i = 0; i < 4; i++) {
        const int k = k0 + ty + i * 8, n = n0 + tx;
        tile[ty + i * 8][tx] = (n < N) ? W[(size_t)k * N + n] : 0.0f;
    }
    __syncthreads();
#pragma unroll
    for (int i = 0; i < 4; i++) {
        const int n = n0 + ty + i * 8, k = k0 + tx;
        const float v = tile[tx][ty + i * 8];
        const __nv_bfloat16 h = __float2bfloat16(v);
        Thi[(size_t)n * KGLOB + k] = h;
        Tlo[(size_t)n * KGLOB + k] = __float2bfloat16(v - __bfloat162float(h));
    }
}

// ---------------- reductions ----------------
__device__ __forceinline__ float warpSum(float v) {
#pragma unroll
    for (int o = 16; o > 0; o >>= 1) v += __shfl_down_sync(0xffffffffu, v, o);
    return v;
}
__device__ __forceinline__ float blockSum(float v, float* sm, int nwarps) {
    int lane = threadIdx.x & 31, w = threadIdx.x >> 5;
    v = warpSum(v);
    __syncthreads();
    if (lane == 0) sm[w] = v;
    __syncthreads();
    if (w == 0) {
        float x = (lane < nwarps) ? sm[lane] : 0.f;
        x = warpSum(x);
        if (lane == 0) sm[0] = x;
    }
    __syncthreads();
    return sm[0];
}

// ---------------- LayerNorm + split output ----------------
__global__ void layernorm_split_kernel(const float* __restrict__ h, const float* __restrict__ g,
                                       const float* __restrict__ beta,
                                       __nv_bfloat162* __restrict__ hi, __nv_bfloat162* __restrict__ lo)
{
    __shared__ float sred[8];
    const int row = blockIdx.x;
    const float* r = h + (size_t)row * H_;
    float4 v = ((const float4*)r)[threadIdx.x];
    float s = v.x + v.y + v.z + v.w;
    s = blockSum(s, sred, 8);
    const float mu = s * (1.0f / H_);
    const float dx = v.x - mu, dy = v.y - mu, dz = v.z - mu, dw = v.w - mu;
    float q = dx * dx + dy * dy + dz * dz + dw * dw;
    q = blockSum(q, sred, 8);
    const float rsig = rsqrtf(q * (1.0f / H_) + 1e-5f);
    const int c = threadIdx.x * 4;
    float ox = dx * rsig * g[c + 0] + beta[c + 0];
    float oy = dy * rsig * g[c + 1] + beta[c + 1];
    float oz = dz * rsig * g[c + 2] + beta[c + 2];
    float ow = dw * rsig * g[c + 3] + beta[c + 3];
    const size_t base = ((size_t)row * H_ + c) / 2;
    __nv_bfloat16 hx = __float2bfloat16(ox), hy = __float2bfloat16(oy);
    __nv_bfloat16 hz = __float2bfloat16(oz), hw = __float2bfloat16(ow);
    hi[base]     = __nv_bfloat162(hx, hy);
    hi[base + 1] = __nv_bfloat162(hz, hw);
    lo[base]     = __nv_bfloat162(__float2bfloat16(ox - __bfloat162float(hx)),
                                  __float2bfloat16(oy - __bfloat162float(hy)));
    lo[base + 1] = __nv_bfloat162(__float2bfloat16(oz - __bfloat162float(hz)),
                                  __float2bfloat16(ow - __bfloat162float(hw)));
}

// ---------------- evidential head ----------------
__device__ __forceinline__ float softplusf(float x) {
    return fmaxf(x, 0.f) + log1pf(__expf(-fabsf(x)));
}
__device__ __forceinline__ float digammaf_(float x) {
    float r = 0.f;
#pragma unroll
    for (int i = 0; i < 5; i++) {
        if (x < 6.f) { r -= __fdividef(1.f, x); x += 1.f; }
    }
    const float inv = __fdividef(1.f, x);
    const float inv2 = inv * inv;
    const float ser = inv2 * (0.0833333333f - inv2 * (0.0083333333f - inv2 * 0.0039682540f));
    return r + logf(x) - 0.5f * inv - ser;
}

__global__ void head_kernel(const float* __restrict__ logits,
                            float* __restrict__ alpha_o, float* __restrict__ evid_o,
                            float* __restrict__ eprob_o, float* __restrict__ vac_o,
                            float* __restrict__ diss_o, float* __restrict__ alea_o)
{
    __shared__ float sb[K_];
    __shared__ float sa[K_];
    __shared__ float sm[4];
    const int row = blockIdx.x;
    const int t = threadIdx.x;

    float e = 0.f, a = 0.f;
    if (t < K_) {
        const float xv = logits[(size_t)row * K_ + t];
        e = softplusf(xv);
        a = e + 1.f;
    }
    const float S = blockSum(a, sm, 4);

    if (t < K_) {
        const size_t o = (size_t)row * K_ + t;
        alpha_o[o] = a;
        evid_o[o] = e;
        eprob_o[o] = a / S;
        sb[t] = e / S;
        sa[t] = a;
    }
    if (t == 0) vac_o[row] = (float)K_ / S;
    __syncthreads();

    // dissonance = sum_{i<j} (1 - |bi-bj|/(bi+bj+eps)) * bi * bj  (exact identity)
    float pairsum = 0.f;
    for (int idx = t; idx < K_ * K_; idx += 128) {
        const int i = idx / K_;
        const int j = idx - i * K_;
        if (i < j) {
            const float bi = sb[i], bj = sb[j];
            const float den = bi + bj + 1e-8f;
            pairsum += (1.f - __fdividef(fabsf(bi - bj), den)) * bi * bj;
        }
    }
    pairsum = blockSum(pairsum, sm, 4);

    const float psiS = digammaf_(S);
    float al = 0.f;
    if (t < K_) al = (sa[t] / S) * (digammaf_(sa[t]) - psiS);
    const float alea = blockSum(al, sm, 4);

    if (t == 0) {
        diss_o[row] = pairsum;
        alea_o[row] = -alea;
    }
}

// ---------------- launch ----------------
extern "C" void kernel_launch(void* const* d_in, const int* in_sizes, int n_in,
                              void* d_out, int out_size)
{
    const float* x    = (const float*)d_in[0];
    const float* W1   = (const float*)d_in[1];
    const float* b1   = (const float*)d_in[2];
    const float* g    = (const float*)d_in[3];
    const float* beta = (const float*)d_in[4];
    const float* W2   = (const float*)d_in[5];
    const float* b2   = (const float*)d_in[6];
    const float* W3   = (const float*)d_in[7];
    const float* b3   = (const float*)d_in[8];

    void *p;
    cudaGetSymbolAddress(&p, g_xhi);  __nv_bfloat16* xhi = (__nv_bfloat16*)p;
    cudaGetSymbolAddress(&p, g_xlo);  __nv_bfloat16* xlo = (__nv_bfloat16*)p;
    cudaGetSymbolAddress(&p, g_h1hi); __nv_bfloat16* h1hi = (__nv_bfloat16*)p;
    cudaGetSymbolAddress(&p, g_h1lo); __nv_bfloat16* h1lo = (__nv_bfloat16*)p;
    cudaGetSymbolAddress(&p, g_h2hi); __nv_bfloat16* h2hi = (__nv_bfloat16*)p;
    cudaGetSymbolAddress(&p, g_h2lo); __nv_bfloat16* h2lo = (__nv_bfloat16*)p;
    cudaGetSymbolAddress(&p, g_w1hi); __nv_bfloat16* w1hi = (__nv_bfloat16*)p;
    cudaGetSymbolAddress(&p, g_w1lo); __nv_bfloat16* w1lo = (__nv_bfloat16*)p;
    cudaGetSymbolAddress(&p, g_w2hi); __nv_bfloat16* w2hi = (__nv_bfloat16*)p;
    cudaGetSymbolAddress(&p, g_w2lo); __nv_bfloat16* w2lo = (__nv_bfloat16*)p;
    cudaGetSymbolAddress(&p, g_w3hi); __nv_bfloat16* w3hi = (__nv_bfloat16*)p;
    cudaGetSymbolAddress(&p, g_w3lo); __nv_bfloat16* w3lo = (__nv_bfloat16*)p;
    cudaGetSymbolAddress(&p, g_h1);   float* h1 = (float*)p;
    cudaGetSymbolAddress(&p, g_lg);   float* lg = (float*)p;

    const int DSMEM = NSTG * (int)STGB;   // 81920
    cudaFuncSetAttribute(gemm_mma, cudaFuncAttributeMaxDynamicSharedMemorySize, DSMEM);

    const int splitBlocks = (B_ * H_) / 4 / 256;   // 8192

    // weight prep (transposed + split)
    transpose_split<<<dim3(32, 32), dim3(32, 8)>>>(W1, w1hi, w1lo, H_);
    transpose_split<<<dim3(32, 32), dim3(32, 8)>>>(W2, w2hi, w2lo, H_);
    transpose_split<<<dim3(4, 32),  dim3(32, 8)>>>(W3, w3hi, w3lo, K_);

    // x split
    split_kernel<<<splitBlocks, 256>>>((const float4*)x, (__nv_bfloat162*)xhi, (__nv_bfloat162*)xlo);

    // GEMM1 + silu -> fp32 h1
    gemm_mma<<<dim3(8, 64), 256, DSMEM>>>(xhi, xlo, w1hi, w1lo, b1, h1, nullptr, nullptr, H_, 1, 0);
    // LayerNorm -> split h1
    layernorm_split_kernel<<<B_, 256>>>(h1, g, beta, (__nv_bfloat162*)h1hi, (__nv_bfloat162*)h1lo);
    // GEMM2 + silu -> split h2 (fused, no fp32 h2)
    gemm_mma<<<dim3(8, 64), 256, DSMEM>>>(h1hi, h1lo, w2hi, w2lo, b2, nullptr, h2hi, h2lo, H_, 1, 1);
    // GEMM3 -> logits fp32
    gemm_mma<<<dim3(1, 64), 256, DSMEM>>>(h2hi, h2lo, w3hi, w3lo, b3, lg, nullptr, nullptr, K_, 0, 0);

    float* out = (float*)d_out;
    const size_t BK = (size_t)B_ * K_;
    head_kernel<<<B_, 128>>>(lg,
                             out,                    // alpha
                             out + BK,               // evidence
                             out + 2 * BK,           // expected_prob
                             out + 3 * BK,           // vacuity
                             out + 3 * BK + B_,      // dissonance
                             out + 3 * BK + 2 * B_); // aleatoric
}

// round 6
// speedup vs baseline: 1.9863x; 1.0318x over previous
#include <cuda_runtime.h>
#include <cuda_bf16.h>
#include <stdint.h>
#include <math.h>

#define B_ 8192
#define D_ 1024
#define H_ 1024
#define K_ 100
#define KGLOB 1024
#define SPLITK 8
#define PSTRIDE ((size_t)B_ * 128)

// ---------------- device scratch ----------------
__device__ uint4  g_xhi [(size_t)B_ * H_ * 2 / 16];
__device__ uint4  g_xlo [(size_t)B_ * H_ * 2 / 16];
__device__ uint4  g_h1hi[(size_t)B_ * H_ * 2 / 16];
__device__ uint4  g_h1lo[(size_t)B_ * H_ * 2 / 16];
__device__ uint4  g_h2hi[(size_t)B_ * H_ * 2 / 16];
__device__ uint4  g_h2lo[(size_t)B_ * H_ * 2 / 16];
__device__ uint4  g_w1hi[(size_t)H_ * KGLOB * 2 / 16];
__device__ uint4  g_w1lo[(size_t)H_ * KGLOB * 2 / 16];
__device__ uint4  g_w2hi[(size_t)H_ * KGLOB * 2 / 16];
__device__ uint4  g_w2lo[(size_t)H_ * KGLOB * 2 / 16];
__device__ uint4  g_w3hi[(size_t)128 * KGLOB * 2 / 16];
__device__ uint4  g_w3lo[(size_t)128 * KGLOB * 2 / 16];
__device__ float4 g_h1  [(size_t)B_ * H_ / 4];   // h1 fp32; reused as GEMM3 split-K partials

// ---------------- helpers ----------------
__device__ __forceinline__ uint32_t smem_u32(const void* p) {
    uint32_t a;
    asm("{ .reg .u64 t; cvta.to.shared.u64 t, %1; cvt.u32.u64 %0, t; }" : "=r"(a) : "l"(p));
    return a;
}
__device__ __forceinline__ void cp16(uint32_t dst, const void* src) {
    asm volatile("cp.async.cg.shared.global [%0], [%1], 16;" :: "r"(dst), "l"(src));
}
__device__ __forceinline__ void ldsm4(uint32_t* r, uint32_t a) {
    asm volatile("ldmatrix.sync.aligned.m8n8.x4.shared.b16 {%0,%1,%2,%3}, [%4];"
                 : "=r"(r[0]), "=r"(r[1]), "=r"(r[2]), "=r"(r[3]) : "r"(a));
}
__device__ __forceinline__ void mma_bf16(float* c, const uint32_t* a, const uint32_t* b) {
    asm volatile("mma.sync.aligned.m16n8k16.row.col.f32.bf16.bf16.f32 "
                 "{%0,%1,%2,%3},{%4,%5,%6,%7},{%8,%9},{%0,%1,%2,%3};"
                 : "+f"(c[0]), "+f"(c[1]), "+f"(c[2]), "+f"(c[3])
                 : "r"(a[0]), "r"(a[1]), "r"(a[2]), "r"(a[3]), "r"(b[0]), "r"(b[1]));
}

// smem tile: 128 rows x 32 bf16, row stride 40 bf16 (80B) -> conflict-free ldmatrix
#define TILEB 10240u          // 128 * 80
#define STGB  40960u          // 4 tiles (Ahi,Alo,Bhi,Blo)
#define NSTG  2

__device__ __forceinline__ void issue_stage(
    uint32_t sbase, int stg,
    const __nv_bfloat16* g0, const __nv_bfloat16* g1,
    const __nv_bfloat16* g2, const __nv_bfloat16* g3,
    int kt, int tid)
{
    const int row = tid >> 1;
    const uint32_t db = sbase + (uint32_t)stg * STGB + (uint32_t)row * 80u + (uint32_t)(tid & 1) * 32u;
    const size_t go = (size_t)row * KGLOB + (size_t)kt * 32 + (size_t)(tid & 1) * 16;
    cp16(db + 0u * TILEB,       g0 + go);
    cp16(db + 0u * TILEB + 16u, g0 + go + 8);
    cp16(db + 1u * TILEB,       g1 + go);
    cp16(db + 1u * TILEB + 16u, g1 + go + 8);
    cp16(db + 2u * TILEB,       g2 + go);
    cp16(db + 2u * TILEB + 16u, g2 + go + 8);
    cp16(db + 3u * TILEB,       g3 + go);
    cp16(db + 3u * TILEB + 16u, g3 + go + 8);
    asm volatile("cp.async.commit_group;" ::: "memory");
}

// ---------------- tensor-core GEMM: out = act(A @ B^T + bias) ----------------
// CTA 128x128, BK=32, 8 warps each 64x32. 3-term split: AhiBhi + AhiBlo + AloBhi.
// splitOut=1: write bf16 hi/lo split. blockIdx.z selects a K-chunk of kIters*32
// (split-K); C is offset by z*partStride.
__global__ __launch_bounds__(256, 2)
void gemm_mma(const __nv_bfloat16* __restrict__ Ahi, const __nv_bfloat16* __restrict__ Alo,
              const __nv_bfloat16* __restrict__ Bhi, const __nv_bfloat16* __restrict__ Blo,
              const float* __restrict__ bias, float* __restrict__ C,
              __nv_bfloat16* __restrict__ Chi, __nv_bfloat16* __restrict__ Clo,
              int Nout, int doSilu, int splitOut, int kIters, size_t partStride)
{
    extern __shared__ __align__(128) char smraw[];
    const uint32_t sbase = smem_u32(smraw);
    const int tid = threadIdx.x, lane = tid & 31, wid = tid >> 5;
    const int warpRow = wid >> 2, warpCol = wid & 3;
    const int rowA = blockIdx.y * 128, rowB = blockIdx.x * 128;
    const int kOff = blockIdx.z * kIters;
    if (partStride) C += (size_t)blockIdx.z * partStride;

    const __nv_bfloat16* g0 = Ahi + (size_t)rowA * KGLOB;
    const __nv_bfloat16* g1 = Alo + (size_t)rowA * KGLOB;
    const __nv_bfloat16* g2 = Bhi + (size_t)rowB * KGLOB;
    const __nv_bfloat16* g3 = Blo + (size_t)rowB * KGLOB;

    float acc[4][4][4];
#pragma unroll
    for (int mt = 0; mt < 4; mt++)
#pragma unroll
        for (int nt = 0; nt < 4; nt++)
#pragma unroll
            for (int i = 0; i < 4; i++) acc[mt][nt][i] = 0.f;

    issue_stage(sbase, 0, g0, g1, g2, g3, kOff, tid);

    const uint32_t aoff_c = (uint32_t)warpRow * 5120u + (uint32_t)(lane & 15) * 80u
                          + (uint32_t)(lane >> 4) * 16u;
    const uint32_t bn = (uint32_t)((lane & 7) | ((lane >> 4) << 3));
    const uint32_t boff_c = ((uint32_t)warpCol * 32u + bn) * 80u + (uint32_t)((lane >> 3) & 1) * 16u;

#pragma unroll 1
    for (int tt = 0; tt < kIters; tt++) {
        asm volatile("cp.async.wait_group 0;" ::: "memory");
        __syncthreads();
        if (tt + 1 < kIters) issue_stage(sbase, (tt + 1) & 1, g0, g1, g2, g3, kOff + tt + 1, tid);

        const uint32_t cb = sbase + (uint32_t)(tt & 1) * STGB;
#pragma unroll
        for (int s = 0; s < 2; s++) {
            uint32_t ah[4][4], al[4][4], bh[4][2], bl[4][2], tmp[4];
            const uint32_t ao = cb + aoff_c + (uint32_t)s * 32u;
#pragma unroll
            for (int mt = 0; mt < 4; mt++) ldsm4(ah[mt], ao + (uint32_t)mt * 1280u);
#pragma unroll
            for (int mt = 0; mt < 4; mt++) ldsm4(al[mt], ao + TILEB + (uint32_t)mt * 1280u);
            const uint32_t bo = cb + 2u * TILEB + boff_c + (uint32_t)s * 32u;
            ldsm4(tmp, bo);
            bh[0][0] = tmp[0]; bh[0][1] = tmp[1]; bh[1][0] = tmp[2]; bh[1][1] = tmp[3];
            ldsm4(tmp, bo + 1280u);
            bh[2][0] = tmp[0]; bh[2][1] = tmp[1]; bh[3][0] = tmp[2]; bh[3][1] = tmp[3];
            ldsm4(tmp, bo + TILEB);
            bl[0][0] = tmp[0]; bl[0][1] = tmp[1]; bl[1][0] = tmp[2]; bl[1][1] = tmp[3];
            ldsm4(tmp, bo + TILEB + 1280u);
            bl[2][0] = tmp[0]; bl[2][1] = tmp[1]; bl[3][0] = tmp[2]; bl[3][1] = tmp[3];
#pragma unroll
            for (int mt = 0; mt < 4; mt++)
#pragma unroll
                for (int nt = 0; nt < 4; nt++) {
                    mma_bf16(acc[mt][nt], ah[mt], bh[nt]);
                    mma_bf16(acc[mt][nt], ah[mt], bl[nt]);
                    mma_bf16(acc[mt][nt], al[mt], bh[nt]);
                }
        }
        __syncthreads();
    }

    // epilogue
#pragma unroll
    for (int mt = 0; mt < 4; mt++) {
        const int row0 = rowA + warpRow * 64 + mt * 16 + (lane >> 2);
#pragma unroll
        for (int nt = 0; nt < 4; nt++) {
            const int col = blockIdx.x * 128 + warpCol * 32 + nt * 8 + (lane & 3) * 2;
            if (col < Nout) {
                const float bx = bias ? bias[col] : 0.f;
                const float by = bias ? bias[col + 1] : 0.f;
                float2 v0, v1;
                v0.x = acc[mt][nt][0] + bx; v0.y = acc[mt][nt][1] + by;
                v1.x = acc[mt][nt][2] + bx; v1.y = acc[mt][nt][3] + by;
                if (doSilu) {
                    v0.x = v0.x / (1.f + __expf(-v0.x));
                    v0.y = v0.y / (1.f + __expf(-v0.y));
                    v1.x = v1.x / (1.f + __expf(-v1.x));
                    v1.y = v1.y / (1.f + __expf(-v1.y));
                }
                if (splitOut) {
                    const size_t o0 = (size_t)row0 * KGLOB + col;
                    const size_t o1 = (size_t)(row0 + 8) * KGLOB + col;
                    __nv_bfloat16 h0x = __float2bfloat16(v0.x), h0y = __float2bfloat16(v0.y);
                    __nv_bfloat16 h1x = __float2bfloat16(v1.x), h1y = __float2bfloat16(v1.y);
                    *(__nv_bfloat162*)(Chi + o0) = __nv_bfloat162(h0x, h0y);
                    *(__nv_bfloat162*)(Chi + o1) = __nv_bfloat162(h1x, h1y);
                    *(__nv_bfloat162*)(Clo + o0) = __nv_bfloat162(
                        __float2bfloat16(v0.x - __bfloat162float(h0x)),
                        __float2bfloat16(v0.y - __bfloat162float(h0y)));
                    *(__nv_bfloat162*)(Clo + o1) = __nv_bfloat162(
                        __float2bfloat16(v1.x - __bfloat162float(h1x)),
                        __float2bfloat16(v1.y - __bfloat162float(h1y)));
                } else {
                    *(float2*)&C[(size_t)row0 * Nout + col] = v0;
                    *(float2*)&C[(size_t)(row0 + 8) * Nout + col] = v1;
                }
            }
        }
    }
}

// ---------------- fp32 -> (hi, lo) bf16 split (input x only) ----------------
__global__ void split_kernel(const float4* __restrict__ src,
                             __nv_bfloat162* __restrict__ hi, __nv_bfloat162* __restrict__ lo)
{
    const size_t i = (size_t)blockIdx.x * 256 + threadIdx.x;
    float4 v = src[i];
    __nv_bfloat16 h0 = __float2bfloat16(v.x), h1 = __float2bfloat16(v.y);
    __nv_bfloat16 h2 = __float2bfloat16(v.z), h3 = __float2bfloat16(v.w);
    hi[2 * i]     = __nv_bfloat162(h0, h1);
    hi[2 * i + 1] = __nv_bfloat162(h2, h3);
    lo[2 * i]     = __nv_bfloat162(__float2bfloat16(v.x - __bfloat162float(h0)),
                                   __float2bfloat16(v.y - __bfloat162float(h1)));
    lo[2 * i + 1] = __nv_bfloat162(__float2bfloat16(v.z - __bfloat162float(h2)),
                                   __float2bfloat16(v.w - __bfloat162float(h3)));
}

// ---------------- W [K,N] fp32 -> transposed split [Npad,K] bf16 ----------------
__global__ void transpose_split(const float* __restrict__ W,
                                __nv_bfloat16* __restrict__ Thi, __nv_bfloat16* __restrict__ Tlo,
                                int N)
{
    __shared__ float tile[32][33];
    const int n0 = blockIdx.x * 32, k0 = blockIdx.y * 32;
    const int tx = threadIdx.x, ty = threadIdx.y;
#pragma unroll
    for (int i = 0; i < 4; i++) {
        const int k = k0 + ty + i * 8, n = n0 + tx;
        tile[ty + i * 8][tx] = (n < N) ? W[(size_t)k * N + n] : 0.0f;
    }
    __syncthreads();
#pragma unroll
    for (int i = 0; i < 4; i++) {
        const int n = n0 + ty + i * 8, k = k0 + tx;
        const float v = tile[tx][ty + i * 8];
        const __nv_bfloat16 h = __float2bfloat16(v);
        Thi[(size_t)n * KGLOB + k] = h;
        Tlo[(size_t)n * KGLOB + k] = __float2bfloat16(v - __bfloat162float(h));
    }
}

// ---------------- reductions ----------------
__device__ __forceinline__ float warpSum(float v) {
#pragma unroll
    for (int o = 16; o > 0; o >>= 1) v += __shfl_down_sync(0xffffffffu, v, o);
    return v;
}
__device__ __forceinline__ float blockSum(float v, float* sm, int nwarps) {
    int lane = threadIdx.x & 31, w = threadIdx.x >> 5;
    v = warpSum(v);
    __syncthreads();
    if (lane == 0) sm[w] = v;
    __syncthreads();
    if (w == 0) {
        float x = (lane < nwarps) ? sm[lane] : 0.f;
        x = warpSum(x);
        if (lane == 0) sm[0] = x;
    }
    __syncthreads();
    return sm[0];
}

// ---------------- LayerNorm + split output ----------------
__global__ void layernorm_split_kernel(const float* __restrict__ h, const float* __restrict__ g,
                                       const float* __restrict__ beta,
                                       __nv_bfloat162* __restrict__ hi, __nv_bfloat162* __restrict__ lo)
{
    __shared__ float sred[8];
    const int row = blockIdx.x;
    const float* r = h + (size_t)row * H_;
    float4 v = ((const float4*)r)[threadIdx.x];
    float s = v.x + v.y + v.z + v.w;
    s = blockSum(s, sred, 8);
    const float mu = s * (1.0f / H_);
    const float dx = v.x - mu, dy = v.y - mu, dz = v.z - mu, dw = v.w - mu;
    float q = dx * dx + dy * dy + dz * dz + dw * dw;
    q = blockSum(q, sred, 8);
    const float rsig = rsqrtf(q * (1.0f / H_) + 1e-5f);
    const int c = threadIdx.x * 4;
    float ox = dx * rsig * g[c + 0] + beta[c + 0];
    float oy = dy * rsig * g[c + 1] + beta[c + 1];
    float oz = dz * rsig * g[c + 2] + beta[c + 2];
    float ow = dw * rsig * g[c + 3] + beta[c + 3];
    const size_t base = ((size_t)row * H_ + c) / 2;
    __nv_bfloat16 hx = __float2bfloat16(ox), hy = __float2bfloat16(oy);
    __nv_bfloat16 hz = __float2bfloat16(oz), hw = __float2bfloat16(ow);
    hi[base]     = __nv_bfloat162(hx, hy);
    hi[base + 1] = __nv_bfloat162(hz, hw);
    lo[base]     = __nv_bfloat162(__float2bfloat16(ox - __bfloat162float(hx)),
                                  __float2bfloat16(oy - __bfloat162float(hy)));
    lo[base + 1] = __nv_bfloat162(__float2bfloat16(oz - __bfloat162float(hz)),
                                  __float2bfloat16(ow - __bfloat162float(hw)));
}

// ---------------- evidential head (reads split-K partials, adds bias) ----------------
__device__ __forceinline__ float softplusf(float x) {
    return fmaxf(x, 0.f) + log1pf(__expf(-fabsf(x)));
}
__device__ __forceinline__ float digammaf_(float x) {
    float r = 0.f;
#pragma unroll
    for (int i = 0; i < 5; i++) {
        if (x < 6.f) { r -= __fdividef(1.f, x); x += 1.f; }
    }
    const float inv = __fdividef(1.f, x);
    const float inv2 = inv * inv;
    const float ser = inv2 * (0.0833333333f - inv2 * (0.0083333333f - inv2 * 0.0039682540f));
    return r + logf(x) - 0.5f * inv - ser;
}

__global__ void head_kernel(const float* __restrict__ partial, const float* __restrict__ b3,
                            float* __restrict__ alpha_o, float* __restrict__ evid_o,
                            float* __restrict__ eprob_o, float* __restrict__ vac_o,
                            float* __restrict__ diss_o, float* __restrict__ alea_o)
{
    __shared__ float sb[K_];
    __shared__ float sa[K_];
    __shared__ float sm[4];
    const int row = blockIdx.x;
    const int t = threadIdx.x;

    float e = 0.f, a = 0.f;
    if (t < K_) {
        float xv = b3[t];
        const float* pp = partial + (size_t)row * 128 + t;
#pragma unroll
        for (int c = 0; c < SPLITK; c++) xv += pp[c * PSTRIDE];
        e = softplusf(xv);
        a = e + 1.f;
    }
    const float S = blockSum(a, sm, 4);

    if (t < K_) {
        const size_t o = (size_t)row * K_ + t;
        alpha_o[o] = a;
        evid_o[o] = e;
        eprob_o[o] = a / S;
        sb[t] = e / S;
        sa[t] = a;
    }
    if (t == 0) vac_o[row] = (float)K_ / S;
    __syncthreads();

    // dissonance = sum_{i<j} (1 - |bi-bj|/(bi+bj+eps)) * bi * bj
    float pairsum = 0.f;
    for (int idx = t; idx < K_ * K_; idx += 128) {
        const int i = idx / K_;
        const int j = idx - i * K_;
        if (i < j) {
            const float bi = sb[i], bj = sb[j];
            const float den = bi + bj + 1e-8f;
            pairsum += (1.f - __fdividef(fabsf(bi - bj), den)) * bi * bj;
        }
    }
    pairsum = blockSum(pairsum, sm, 4);

    const float psiS = digammaf_(S);
    float al = 0.f;
    if (t < K_) al = (sa[t] / S) * (digammaf_(sa[t]) - psiS);
    const float alea = blockSum(al, sm, 4);

    if (t == 0) {
        diss_o[row] = pairsum;
        alea_o[row] = -alea;
    }
}

// ---------------- launch ----------------
extern "C" void kernel_launch(void* const* d_in, const int* in_sizes, int n_in,
                              void* d_out, int out_size)
{
    const float* x    = (const float*)d_in[0];
    const float* W1   = (const float*)d_in[1];
    const float* b1   = (const float*)d_in[2];
    const float* g    = (const float*)d_in[3];
    const float* beta = (const float*)d_in[4];
    const float* W2   = (const float*)d_in[5];
    const float* b2   = (const float*)d_in[6];
    const float* W3   = (const float*)d_in[7];
    const float* b3   = (const float*)d_in[8];

    void *p;
    cudaGetSymbolAddress(&p, g_xhi);  __nv_bfloat16* xhi = (__nv_bfloat16*)p;
    cudaGetSymbolAddress(&p, g_xlo);  __nv_bfloat16* xlo = (__nv_bfloat16*)p;
    cudaGetSymbolAddress(&p, g_h1hi); __nv_bfloat16* h1hi = (__nv_bfloat16*)p;
    cudaGetSymbolAddress(&p, g_h1lo); __nv_bfloat16* h1lo = (__nv_bfloat16*)p;
    cudaGetSymbolAddress(&p, g_h2hi); __nv_bfloat16* h2hi = (__nv_bfloat16*)p;
    cudaGetSymbolAddress(&p, g_h2lo); __nv_bfloat16* h2lo = (__nv_bfloat16*)p;
    cudaGetSymbolAddress(&p, g_w1hi); __nv_bfloat16* w1hi = (__nv_bfloat16*)p;
    cudaGetSymbolAddress(&p, g_w1lo); __nv_bfloat16* w1lo = (__nv_bfloat16*)p;
    cudaGetSymbolAddress(&p, g_w2hi); __nv_bfloat16* w2hi = (__nv_bfloat16*)p;
    cudaGetSymbolAddress(&p, g_w2lo); __nv_bfloat16* w2lo = (__nv_bfloat16*)p;
    cudaGetSymbolAddress(&p, g_w3hi); __nv_bfloat16* w3hi = (__nv_bfloat16*)p;
    cudaGetSymbolAddress(&p, g_w3lo); __nv_bfloat16* w3lo = (__nv_bfloat16*)p;
    cudaGetSymbolAddress(&p, g_h1);   float* h1 = (float*)p;   // also GEMM3 partials

    const int DSMEM = NSTG * (int)STGB;   // 81920
    cudaFuncSetAttribute(gemm_mma, cudaFuncAttributeMaxDynamicSharedMemorySize, DSMEM);

    const int splitBlocks = (B_ * H_) / 4 / 256;   // 8192

    // weight prep (transposed + split)
    transpose_split<<<dim3(32, 32), dim3(32, 8)>>>(W1, w1hi, w1lo, H_);
    transpose_split<<<dim3(32, 32), dim3(32, 8)>>>(W2, w2hi, w2lo, H_);
    transpose_split<<<dim3(4, 32),  dim3(32, 8)>>>(W3, w3hi, w3lo, K_);

    // x split
    split_kernel<<<splitBlocks, 256>>>((const float4*)x, (__nv_bfloat162*)xhi, (__nv_bfloat162*)xlo);

    // GEMM1 + silu -> fp32 h1
    gemm_mma<<<dim3(8, 64, 1), 256, DSMEM>>>(xhi, xlo, w1hi, w1lo, b1, h1,
                                             nullptr, nullptr, H_, 1, 0, 32, 0);
    // LayerNorm -> split h1
    layernorm_split_kernel<<<B_, 256>>>(h1, g, beta, (__nv_bfloat162*)h1hi, (__nv_bfloat162*)h1lo);
    // GEMM2 + silu -> split h2 (fused)
    gemm_mma<<<dim3(8, 64, 1), 256, DSMEM>>>(h1hi, h1lo, w2hi, w2lo, b2, nullptr,
                                             h2hi, h2lo, H_, 1, 1, 32, 0);
    // GEMM3 split-K=8 -> partials in h1 buffer (h1 dead after LN split)
    gemm_mma<<<dim3(1, 64, SPLITK), 256, DSMEM>>>(h2hi, h2lo, w3hi, w3lo, nullptr, h1,
                                                  nullptr, nullptr, 128, 0, 0,
                                                  32 / SPLITK, PSTRIDE);

    float* out = (float*)d_out;
    const size_t BK = (size_t)B_ * K_;
    head_kernel<<<B_, 128>>>(h1, b3,
                             out,                    // alpha
                             out + BK,               // evidence
                             out + 2 * BK,           // expected_prob
                             out + 3 * BK,           // vacuity
                             out + 3 * BK + B_,      // dissonance
                             out + 3 * BK + 2 * B_); // aleatoric
}

// round 7
// speedup vs baseline: 2.6019x; 1.3099x over previous
#include <cuda_runtime.h>
#include <cuda_fp16.h>
#include <stdint.h>
#include <math.h>

#define B_ 8192
#define D_ 1024
#define H_ 1024
#define K_ 100
#define KGLOB 1024
#define SPLITK 8
#define PSTRIDE ((size_t)B_ * 128)

// ---------------- device scratch ----------------
__device__ uint4 g_xhi [(size_t)B_ * H_ * 2 / 16];
__device__ uint4 g_h1hi[(size_t)B_ * H_ * 2 / 16];
__device__ uint4 g_h2hi[(size_t)B_ * H_ * 2 / 16];
__device__ uint4 g_w1hi[(size_t)H_ * KGLOB * 2 / 16];
__device__ uint4 g_w1lo[(size_t)H_ * KGLOB * 2 / 16];
__device__ uint4 g_w2hi[(size_t)H_ * KGLOB * 2 / 16];
__device__ uint4 g_w2lo[(size_t)H_ * KGLOB * 2 / 16];
__device__ uint4 g_w3hi[(size_t)128 * KGLOB * 2 / 16];
__device__ uint4 g_w3lo[(size_t)128 * KGLOB * 2 / 16];
__device__ float4 g_h1 [(size_t)B_ * H_ / 4];   // h1 fp32; reused as GEMM3 split-K partials

// ---------------- helpers ----------------
__device__ __forceinline__ uint32_t smem_u32(const void* p) {
    uint32_t a;
    asm("{ .reg .u64 t; cvta.to.shared.u64 t, %1; cvt.u32.u64 %0, t; }" : "=r"(a) : "l"(p));
    return a;
}
__device__ __forceinline__ void cp16(uint32_t dst, const void* src) {
    asm volatile("cp.async.cg.shared.global [%0], [%1], 16;" :: "r"(dst), "l"(src));
}
__device__ __forceinline__ void ldsm4(uint32_t* r, uint32_t a) {
    asm volatile("ldmatrix.sync.aligned.m8n8.x4.shared.b16 {%0,%1,%2,%3}, [%4];"
                 : "=r"(r[0]), "=r"(r[1]), "=r"(r[2]), "=r"(r[3]) : "r"(a));
}
__device__ __forceinline__ void mma_f16(float* c, const uint32_t* a, const uint32_t* b) {
    asm volatile("mma.sync.aligned.m16n8k16.row.col.f32.f16.f16.f32 "
                 "{%0,%1,%2,%3},{%4,%5,%6,%7},{%8,%9},{%0,%1,%2,%3};"
                 : "+f"(c[0]), "+f"(c[1]), "+f"(c[2]), "+f"(c[3])
                 : "r"(a[0]), "r"(a[1]), "r"(a[2]), "r"(a[3]), "r"(b[0]), "r"(b[1]));
}

// smem tile: 128 rows x 32 fp16, row stride 40 halves (80B) -> conflict-free ldmatrix
#define TILEB 10240u          // 128 * 80
#define STGB  30720u          // 3 tiles (Ahi, Bhi, Blo)
#define NSTG  3

__device__ __forceinline__ void issue_stage(
    uint32_t sbase, int stg,
    const __half* gA, const __half* gBh, const __half* gBl,
    int kt, int tid)
{
    const int row = tid >> 1;
    const uint32_t db = sbase + (uint32_t)stg * STGB + (uint32_t)row * 80u + (uint32_t)(tid & 1) * 32u;
    const size_t go = (size_t)row * KGLOB + (size_t)kt * 32 + (size_t)(tid & 1) * 16;
    cp16(db + 0u * TILEB,       gA + go);
    cp16(db + 0u * TILEB + 16u, gA + go + 8);
    cp16(db + 1u * TILEB,       gBh + go);
    cp16(db + 1u * TILEB + 16u, gBh + go + 8);
    cp16(db + 2u * TILEB,       gBl + go);
    cp16(db + 2u * TILEB + 16u, gBl + go + 8);
    asm volatile("cp.async.commit_group;" ::: "memory");
}

// ---------------- tensor-core GEMM: out = act(A @ B^T + bias) ----------------
// A hi fp16 [M,1024]; B hi/lo fp16 [Npad,1024] (pre-transposed weights).
// 2-term split: A·Bhi + A·Blo. CTA 128x128, BK=32, 8 warps each 64x32.
// splitOut=1: write fp16 Chi. blockIdx.z = split-K chunk (kIters*32 wide).
__global__ __launch_bounds__(256, 2)
void gemm_mma(const __half* __restrict__ Ahi,
              const __half* __restrict__ Bhi, const __half* __restrict__ Blo,
              const float* __restrict__ bias, float* __restrict__ C,
              __half* __restrict__ Chi,
              int Nout, int doSilu, int splitOut, int kIters, size_t partStride)
{
    extern __shared__ __align__(128) char smraw[];
    const uint32_t sbase = smem_u32(smraw);
    const int tid = threadIdx.x, lane = tid & 31, wid = tid >> 5;
    const int warpRow = wid >> 2, warpCol = wid & 3;
    const int rowA = blockIdx.y * 128, rowB = blockIdx.x * 128;
    const int kOff = blockIdx.z * kIters;
    if (partStride) C += (size_t)blockIdx.z * partStride;

    const __half* gA  = Ahi + (size_t)rowA * KGLOB;
    const __half* gBh = Bhi + (size_t)rowB * KGLOB;
    const __half* gBl = Blo + (size_t)rowB * KGLOB;

    float acc[4][4][4];
#pragma unroll
    for (int mt = 0; mt < 4; mt++)
#pragma unroll
        for (int nt = 0; nt < 4; nt++)
#pragma unroll
            for (int i = 0; i < 4; i++) acc[mt][nt][i] = 0.f;

    issue_stage(sbase, 0, gA, gBh, gBl, kOff, tid);
    issue_stage(sbase, 1, gA, gBh, gBl, kOff + 1, tid);

    const uint32_t aoff_c = (uint32_t)warpRow * 5120u + (uint32_t)(lane & 15) * 80u
                          + (uint32_t)(lane >> 4) * 16u;
    const uint32_t bn = (uint32_t)((lane & 7) | ((lane >> 4) << 3));
    const uint32_t boff_c = ((uint32_t)warpCol * 32u + bn) * 80u + (uint32_t)((lane >> 3) & 1) * 16u;

#pragma unroll 1
    for (int tt = 0; tt < kIters; tt++) {
        asm volatile("cp.async.wait_group 1;" ::: "memory");
        __syncthreads();
        if (tt + 2 < kIters) issue_stage(sbase, (tt + 2) % NSTG, gA, gBh, gBl, kOff + tt + 2, tid);
        else asm volatile("cp.async.commit_group;" ::: "memory");

        const uint32_t cb = sbase + (uint32_t)(tt % NSTG) * STGB;
#pragma unroll
        for (int s = 0; s < 2; s++) {
            uint32_t ah[4][4], bh[4][2], bl[4][2], tmp[4];
            const uint32_t ao = cb + aoff_c + (uint32_t)s * 32u;
#pragma unroll
            for (int mt = 0; mt < 4; mt++) ldsm4(ah[mt], ao + (uint32_t)mt * 1280u);
            const uint32_t bo = cb + 1u * TILEB + boff_c + (uint32_t)s * 32u;
            ldsm4(tmp, bo);
            bh[0][0] = tmp[0]; bh[0][1] = tmp[1]; bh[1][0] = tmp[2]; bh[1][1] = tmp[3];
            ldsm4(tmp, bo + 1280u);
            bh[2][0] = tmp[0]; bh[2][1] = tmp[1]; bh[3][0] = tmp[2]; bh[3][1] = tmp[3];
            ldsm4(tmp, bo + TILEB);
            bl[0][0] = tmp[0]; bl[0][1] = tmp[1]; bl[1][0] = tmp[2]; bl[1][1] = tmp[3];
            ldsm4(tmp, bo + TILEB + 1280u);
            bl[2][0] = tmp[0]; bl[2][1] = tmp[1]; bl[3][0] = tmp[2]; bl[3][1] = tmp[3];
#pragma unroll
            for (int mt = 0; mt < 4; mt++)
#pragma unroll
                for (int nt = 0; nt < 4; nt++) {
                    mma_f16(acc[mt][nt], ah[mt], bh[nt]);
                    mma_f16(acc[mt][nt], ah[mt], bl[nt]);
                }
        }
    }

    // epilogue
#pragma unroll
    for (int mt = 0; mt < 4; mt++) {
        const int row0 = rowA + warpRow * 64 + mt * 16 + (lane >> 2);
#pragma unroll
        for (int nt = 0; nt < 4; nt++) {
            const int col = blockIdx.x * 128 + warpCol * 32 + nt * 8 + (lane & 3) * 2;
            if (col < Nout) {
                const float bx = bias ? bias[col] : 0.f;
                const float by = bias ? bias[col + 1] : 0.f;
                float2 v0, v1;
                v0.x = acc[mt][nt][0] + bx; v0.y = acc[mt][nt][1] + by;
                v1.x = acc[mt][nt][2] + bx; v1.y = acc[mt][nt][3] + by;
                if (doSilu) {
                    v0.x = v0.x / (1.f + __expf(-v0.x));
                    v0.y = v0.y / (1.f + __expf(-v0.y));
                    v1.x = v1.x / (1.f + __expf(-v1.x));
                    v1.y = v1.y / (1.f + __expf(-v1.y));
                }
                if (splitOut) {
                    const size_t o0 = (size_t)row0 * KGLOB + col;
                    const size_t o1 = (size_t)(row0 + 8) * KGLOB + col;
                    *(__half2*)(Chi + o0) = __halves2half2(__float2half(v0.x), __float2half(v0.y));
                    *(__half2*)(Chi + o1) = __halves2half2(__float2half(v1.x), __float2half(v1.y));
                } else {
                    *(float2*)&C[(size_t)row0 * Nout + col] = v0;
                    *(float2*)&C[(size_t)(row0 + 8) * Nout + col] = v1;
                }
            }
        }
    }
}

// ---------------- fp32 -> fp16 hi (input x only) ----------------
__global__ void split_kernel(const float4* __restrict__ src, __half2* __restrict__ hi)
{
    const size_t i = (size_t)blockIdx.x * 256 + threadIdx.x;
    float4 v = src[i];
    hi[2 * i]     = __halves2half2(__float2half(v.x), __float2half(v.y));
    hi[2 * i + 1] = __halves2half2(__float2half(v.z), __float2half(v.w));
}

// ---------------- W [K,N] fp32 -> transposed split [Npad,K] fp16 hi/lo ----------------
__global__ void transpose_split(const float* __restrict__ W,
                                __half* __restrict__ Thi, __half* __restrict__ Tlo, int N)
{
    __shared__ float tile[32][33];
    const int n0 = blockIdx.x * 32, k0 = blockIdx.y * 32;
    const int tx = threadIdx.x, ty = threadIdx.y;
#pragma unroll
    for (int i = 0; i < 4; i++) {
        const int k = k0 + ty + i * 8, n = n0 + tx;
        tile[ty + i * 8][tx] = (n < N) ? W[(size_t)k * N + n] : 0.0f;
    }
    __syncthreads();
#pragma unroll
    for (int i = 0; i < 4; i++) {
        const int n = n0 + ty + i * 8, k = k0 + tx;
        const float v = tile[tx][ty + i * 8];
        const __half h = __float2half(v);
        Thi[(size_t)n * KGLOB + k] = h;
        Tlo[(size_t)n * KGLOB + k] = __float2half(v - __half2float(h));
    }
}

// ---------------- reductions ----------------
__device__ __forceinline__ float warpSum(float v) {
#pragma unroll
    for (int o = 16; o > 0; o >>= 1) v += __shfl_down_sync(0xffffffffu, v, o);
    return v;
}
__device__ __forceinline__ float blockSum(float v, float* sm, int nwarps) {
    int lane = threadIdx.x & 31, w = threadIdx.x >> 5;
    v = warpSum(v);
    __syncthreads();
    if (lane == 0) sm[w] = v;
    __syncthreads();
    if (w == 0) {
        float x = (lane < nwarps) ? sm[lane] : 0.f;
        x = warpSum(x);
        if (lane == 0) sm[0] = x;
    }
    __syncthreads();
    return sm[0];
}

// ---------------- LayerNorm -> fp16 hi ----------------
__global__ void layernorm_split_kernel(const float* __restrict__ h, const float* __restrict__ g,
                                       const float* __restrict__ beta, __half2* __restrict__ hi)
{
    __shared__ float sred[8];
    const int row = blockIdx.x;
    const float* r = h + (size_t)row * H_;
    float4 v = ((const float4*)r)[threadIdx.x];
    float s = v.x + v.y + v.z + v.w;
    s = blockSum(s, sred, 8);
    const float mu = s * (1.0f / H_);
    const float dx = v.x - mu, dy = v.y - mu, dz = v.z - mu, dw = v.w - mu;
    float q = dx * dx + dy * dy + dz * dz + dw * dw;
    q = blockSum(q, sred, 8);
    const float rsig = rsqrtf(q * (1.0f / H_) + 1e-5f);
    const int c = threadIdx.x * 4;
    float ox = dx * rsig * g[c + 0] + beta[c + 0];
    float oy = dy * rsig * g[c + 1] + beta[c + 1];
    float oz = dz * rsig * g[c + 2] + beta[c + 2];
    float ow = dw * rsig * g[c + 3] + beta[c + 3];
    const size_t base = ((size_t)row * H_ + c) / 2;
    hi[base]     = __halves2half2(__float2half(ox), __float2half(oy));
    hi[base + 1] = __halves2half2(__float2half(oz), __float2half(ow));
}

// ---------------- evidential head (reads split-K partials, adds bias) ----------------
__device__ __forceinline__ float softplusf(float x) {
    return fmaxf(x, 0.f) + log1pf(__expf(-fabsf(x)));
}
__device__ __forceinline__ float digammaf_(float x) {
    float r = 0.f;
#pragma unroll
    for (int i = 0; i < 5; i++) {
        if (x < 6.f) { r -= __fdividef(1.f, x); x += 1.f; }
    }
    const float inv = __fdividef(1.f, x);
    const float inv2 = inv * inv;
    const float ser = inv2 * (0.0833333333f - inv2 * (0.0083333333f - inv2 * 0.0039682540f));
    return r + logf(x) - 0.5f * inv - ser;
}

__global__ void head_kernel(const float* __restrict__ partial, const float* __restrict__ b3,
                            float* __restrict__ alpha_o, float* __restrict__ evid_o,
                            float* __restrict__ eprob_o, float* __restrict__ vac_o,
                            float* __restrict__ diss_o, float* __restrict__ alea_o)
{
    __shared__ float sb[K_];
    __shared__ float sa[K_];
    __shared__ float sm[4];
    const int row = blockIdx.x;
    const int t = threadIdx.x;

    float e = 0.f, a = 0.f;
    if (t < K_) {
        float xv = b3[t];
        const float* pp = partial + (size_t)row * 128 + t;
#pragma unroll
        for (int c = 0; c < SPLITK; c++) xv += pp[c * PSTRIDE];
        e = softplusf(xv);
        a = e + 1.f;
    }
    const float S = blockSum(a, sm, 4);

    if (t < K_) {
        const size_t o = (size_t)row * K_ + t;
        alpha_o[o] = a;
        evid_o[o] = e;
        eprob_o[o] = a / S;
        sb[t] = e / S;
        sa[t] = a;
    }
    if (t == 0) vac_o[row] = (float)K_ / S;
    __syncthreads();

    float pairsum = 0.f;
    for (int idx = t; idx < K_ * K_; idx += 128) {
        const int i = idx / K_;
        const int j = idx - i * K_;
        if (i < j) {
            const float bi = sb[i], bj = sb[j];
            const float den = bi + bj + 1e-8f;
            pairsum += (1.f - __fdividef(fabsf(bi - bj), den)) * bi * bj;
        }
    }
    pairsum = blockSum(pairsum, sm, 4);

    const float psiS = digammaf_(S);
    float al = 0.f;
    if (t < K_) al = (sa[t] / S) * (digammaf_(sa[t]) - psiS);
    const float alea = blockSum(al, sm, 4);

    if (t == 0) {
        diss_o[row] = pairsum;
        alea_o[row] = -alea;
    }
}

// ---------------- launch ----------------
extern "C" void kernel_launch(void* const* d_in, const int* in_sizes, int n_in,
                              void* d_out, int out_size)
{
    const float* x    = (const float*)d_in[0];
    const float* W1   = (const float*)d_in[1];
    const float* b1   = (const float*)d_in[2];
    const float* g    = (const float*)d_in[3];
    const float* beta = (const float*)d_in[4];
    const float* W2   = (const float*)d_in[5];
    const float* b2   = (const float*)d_in[6];
    const float* W3   = (const float*)d_in[7];
    const float* b3   = (const float*)d_in[8];

    void *p;
    cudaGetSymbolAddress(&p, g_xhi);  __half* xhi  = (__half*)p;
    cudaGetSymbolAddress(&p, g_h1hi); __half* h1hi = (__half*)p;
    cudaGetSymbolAddress(&p, g_h2hi); __half* h2hi = (__half*)p;
    cudaGetSymbolAddress(&p, g_w1hi); __half* w1hi = (__half*)p;
    cudaGetSymbolAddress(&p, g_w1lo); __half* w1lo = (__half*)p;
    cudaGetSymbolAddress(&p, g_w2hi); __half* w2hi = (__half*)p;
    cudaGetSymbolAddress(&p, g_w2lo); __half* w2lo = (__half*)p;
    cudaGetSymbolAddress(&p, g_w3hi); __half* w3hi = (__half*)p;
    cudaGetSymbolAddress(&p, g_w3lo); __half* w3lo = (__half*)p;
    cudaGetSymbolAddress(&p, g_h1);   float* h1 = (float*)p;   // also GEMM3 partials

    const int DSMEM = NSTG * (int)STGB;   // 92160
    cudaFuncSetAttribute(gemm_mma, cudaFuncAttributeMaxDynamicSharedMemorySize, DSMEM);

    const int splitBlocks = (B_ * H_) / 4 / 256;   // 8192

    // weight prep (transposed + fp16 hi/lo split)
    transpose_split<<<dim3(32, 32), dim3(32, 8)>>>(W1, w1hi, w1lo, H_);
    transpose_split<<<dim3(32, 32), dim3(32, 8)>>>(W2, w2hi, w2lo, H_);
    transpose_split<<<dim3(4, 32),  dim3(32, 8)>>>(W3, w3hi, w3lo, K_);

    // x -> fp16 hi
    split_kernel<<<splitBlocks, 256>>>((const float4*)x, (__half2*)xhi);

    // GEMM1 + silu -> fp32 h1
    gemm_mma<<<dim3(8, 64, 1), 256, DSMEM>>>(xhi, w1hi, w1lo, b1, h1,
                                             nullptr, H_, 1, 0, 32, 0);
    // LayerNorm -> fp16 h1hi
    layernorm_split_kernel<<<B_, 256>>>(h1, g, beta, (__half2*)h1hi);
    // GEMM2 + silu -> fp16 h2hi (fused)
    gemm_mma<<<dim3(8, 64, 1), 256, DSMEM>>>(h1hi, w2hi, w2lo, b2, nullptr,
                                             h2hi, H_, 1, 1, 32, 0);
    // GEMM3 split-K=8 -> partials in h1 buffer
    gemm_mma<<<dim3(1, 64, SPLITK), 256, DSMEM>>>(h2hi, w3hi, w3lo, nullptr, h1,
                                                  nullptr, 128, 0, 0, 32 / SPLITK, PSTRIDE);

    float* out = (float*)d_out;
    const size_t BK = (size_t)B_ * K_;
    head_kernel<<<B_, 128>>>(h1, b3,
                             out,                    // alpha
                             out + BK,               // evidence
                             out + 2 * BK,           // expected_prob
                             out + 3 * BK,           // vacuity
                             out + 3 * BK + B_,      // dissonance
                             out + 3 * BK + 2 * B_); // aleatoric
}

// round 8
// speedup vs baseline: 3.2916x; 1.2651x over previous
#include <cuda_runtime.h>
#include <cuda_fp16.h>
#include <stdint.h>
#include <math.h>

#define B_ 8192
#define D_ 1024
#define H_ 1024
#define K_ 100
#define KGLOB 1024
#define SPLITK 8
#define PSTRIDE ((size_t)B_ * 128)

// ---------------- device scratch ----------------
__device__ uint4 g_xhi [(size_t)B_ * H_ * 2 / 16];
__device__ uint4 g_h1hi[(size_t)B_ * H_ * 2 / 16];
__device__ uint4 g_h2hi[(size_t)B_ * H_ * 2 / 16];
__device__ uint4 g_w1hi[(size_t)H_ * KGLOB * 2 / 16];
__device__ uint4 g_w2hi[(size_t)H_ * KGLOB * 2 / 16];
__device__ uint4 g_w3hi[(size_t)128 * KGLOB * 2 / 16];
__device__ float4 g_part[(size_t)SPLITK * B_ * 128 / 4];   // GEMM3 split-K partials

// ---------------- helpers ----------------
__device__ __forceinline__ uint32_t smem_u32(const void* p) {
    uint32_t a;
    asm("{ .reg .u64 t; cvta.to.shared.u64 t, %1; cvt.u32.u64 %0, t; }" : "=r"(a) : "l"(p));
    return a;
}
__device__ __forceinline__ void cp16(uint32_t dst, const void* src) {
    asm volatile("cp.async.cg.shared.global [%0], [%1], 16;" :: "r"(dst), "l"(src));
}
__device__ __forceinline__ void ldsm4(uint32_t* r, uint32_t a) {
    asm volatile("ldmatrix.sync.aligned.m8n8.x4.shared.b16 {%0,%1,%2,%3}, [%4];"
                 : "=r"(r[0]), "=r"(r[1]), "=r"(r[2]), "=r"(r[3]) : "r"(a));
}
__device__ __forceinline__ void mma_f16(float* c, const uint32_t* a, const uint32_t* b) {
    asm volatile("mma.sync.aligned.m16n8k16.row.col.f32.f16.f16.f32 "
                 "{%0,%1,%2,%3},{%4,%5,%6,%7},{%8,%9},{%0,%1,%2,%3};"
                 : "+f"(c[0]), "+f"(c[1]), "+f"(c[2]), "+f"(c[3])
                 : "r"(a[0]), "r"(a[1]), "r"(a[2]), "r"(a[3]), "r"(b[0]), "r"(b[1]));
}

// smem tile: 128 rows x 64 fp16 (128B) at row stride 144B -> 16B-aligned, conflict-free
#define RSTRIDE 144u
#define TILEB   18432u        // 128 * 144
#define STGB    36864u        // 2 tiles (A, B)
#define NSTG    3

__device__ __forceinline__ void issue_stage(
    uint32_t sbase, int stg,
    const __half* gA, const __half* gB, int kt, int tid)
{
    const int row = tid >> 1;
    const int half64 = (tid & 1);                // which 64B half of the 128B row
    const uint32_t db = sbase + (uint32_t)stg * STGB + (uint32_t)row * RSTRIDE + (uint32_t)half64 * 64u;
    const size_t go = (size_t)row * KGLOB + (size_t)kt * 64 + (size_t)half64 * 32;
#pragma unroll
    for (int i = 0; i < 4; i++) cp16(db + 0u * TILEB + i * 16u, gA + go + i * 8);
#pragma unroll
    for (int i = 0; i < 4; i++) cp16(db + 1u * TILEB + i * 16u, gB + go + i * 8);
    asm volatile("cp.async.commit_group;" ::: "memory");
}

// ---------------- fp16 tensor-core GEMM: out = act(A @ B^T + bias) ----------------
// A fp16 [M,1024]; B fp16 [Npad,1024] (pre-transposed weights).
// CTA 128x128, BK=64, 8 warps each 64x32, 3-stage cp.async pipeline.
// splitOut=1: write fp16 Chi (stride KGLOB). blockIdx.z = split-K chunk.
__global__ __launch_bounds__(256, 2)
void gemm_mma(const __half* __restrict__ A, const __half* __restrict__ Bw,
              const float* __restrict__ bias, float* __restrict__ C,
              __half* __restrict__ Chi,
              int Nout, int doSilu, int splitOut, int kIters, size_t partStride)
{
    extern __shared__ __align__(128) char smraw[];
    const uint32_t sbase = smem_u32(smraw);
    const int tid = threadIdx.x, lane = tid & 31, wid = tid >> 5;
    const int warpRow = wid >> 2, warpCol = wid & 3;
    const int rowA = blockIdx.y * 128, rowB = blockIdx.x * 128;
    const int kOff = blockIdx.z * kIters;
    if (partStride) C += (size_t)blockIdx.z * partStride;

    const __half* gA = A  + (size_t)rowA * KGLOB;
    const __half* gB = Bw + (size_t)rowB * KGLOB;

    float acc[4][4][4];
#pragma unroll
    for (int mt = 0; mt < 4; mt++)
#pragma unroll
        for (int nt = 0; nt < 4; nt++)
#pragma unroll
            for (int i = 0; i < 4; i++) acc[mt][nt][i] = 0.f;

    issue_stage(sbase, 0, gA, gB, kOff, tid);
    issue_stage(sbase, 1, gA, gB, kOff + 1, tid);

    const uint32_t aoff_c = (uint32_t)warpRow * (64u * RSTRIDE)
                          + (uint32_t)(lane & 15) * RSTRIDE + (uint32_t)(lane >> 4) * 16u;
    const uint32_t bn = (uint32_t)((lane & 7) | ((lane >> 4) << 3));
    const uint32_t boff_c = ((uint32_t)warpCol * 32u + bn) * RSTRIDE + (uint32_t)((lane >> 3) & 1) * 16u;

#pragma unroll 1
    for (int tt = 0; tt < kIters; tt++) {
        asm volatile("cp.async.wait_group 1;" ::: "memory");
        __syncthreads();
        if (tt + 2 < kIters) issue_stage(sbase, (tt + 2) % NSTG, gA, gB, kOff + tt + 2, tid);
        else asm volatile("cp.async.commit_group;" ::: "memory");

        const uint32_t cb = sbase + (uint32_t)(tt % NSTG) * STGB;
#pragma unroll
        for (int s = 0; s < 4; s++) {
            uint32_t ah[4][4], bh[4][2], tmp[4];
            const uint32_t ao = cb + aoff_c + (uint32_t)s * 32u;
#pragma unroll
            for (int mt = 0; mt < 4; mt++) ldsm4(ah[mt], ao + (uint32_t)mt * (16u * RSTRIDE));
            const uint32_t bo = cb + 1u * TILEB + boff_c + (uint32_t)s * 32u;
            ldsm4(tmp, bo);
            bh[0][0] = tmp[0]; bh[0][1] = tmp[1]; bh[1][0] = tmp[2]; bh[1][1] = tmp[3];
            ldsm4(tmp, bo + 16u * RSTRIDE);
            bh[2][0] = tmp[0]; bh[2][1] = tmp[1]; bh[3][0] = tmp[2]; bh[3][1] = tmp[3];
#pragma unroll
            for (int mt = 0; mt < 4; mt++)
#pragma unroll
                for (int nt = 0; nt < 4; nt++)
                    mma_f16(acc[mt][nt], ah[mt], bh[nt]);
        }
    }

    // epilogue
#pragma unroll
    for (int mt = 0; mt < 4; mt++) {
        const int row0 = rowA + warpRow * 64 + mt * 16 + (lane >> 2);
#pragma unroll
        for (int nt = 0; nt < 4; nt++) {
            const int col = blockIdx.x * 128 + warpCol * 32 + nt * 8 + (lane & 3) * 2;
            if (col < Nout) {
                const float bx = bias ? bias[col] : 0.f;
                const float by = bias ? bias[col + 1] : 0.f;
                float2 v0, v1;
                v0.x = acc[mt][nt][0] + bx; v0.y = acc[mt][nt][1] + by;
                v1.x = acc[mt][nt][2] + bx; v1.y = acc[mt][nt][3] + by;
                if (doSilu) {
                    v0.x = v0.x / (1.f + __expf(-v0.x));
                    v0.y = v0.y / (1.f + __expf(-v0.y));
                    v1.x = v1.x / (1.f + __expf(-v1.x));
                    v1.y = v1.y / (1.f + __expf(-v1.y));
                }
                if (splitOut) {
                    const size_t o0 = (size_t)row0 * KGLOB + col;
                    const size_t o1 = (size_t)(row0 + 8) * KGLOB + col;
                    *(__half2*)(Chi + o0) = __halves2half2(__float2half(v0.x), __float2half(v0.y));
                    *(__half2*)(Chi + o1) = __halves2half2(__float2half(v1.x), __float2half(v1.y));
                } else {
                    *(float2*)&C[(size_t)row0 * Nout + col] = v0;
                    *(float2*)&C[(size_t)(row0 + 8) * Nout + col] = v1;
                }
            }
        }
    }
}

// ---------------- fp32 -> fp16 (input x) ----------------
__global__ void split_kernel(const float4* __restrict__ src, __half2* __restrict__ hi)
{
    const size_t i = (size_t)blockIdx.x * 256 + threadIdx.x;
    float4 v = src[i];
    hi[2 * i]     = __halves2half2(__float2half(v.x), __float2half(v.y));
    hi[2 * i + 1] = __halves2half2(__float2half(v.z), __float2half(v.w));
}

// ---------------- W [K,N] fp32 -> transposed [Npad,K] fp16 ----------------
__global__ void transpose_hi(const float* __restrict__ W, __half* __restrict__ T, int N)
{
    __shared__ float tile[32][33];
    const int n0 = blockIdx.x * 32, k0 = blockIdx.y * 32;
    const int tx = threadIdx.x, ty = threadIdx.y;
#pragma unroll
    for (int i = 0; i < 4; i++) {
        const int k = k0 + ty + i * 8, n = n0 + tx;
        tile[ty + i * 8][tx] = (n < N) ? W[(size_t)k * N + n] : 0.0f;
    }
    __syncthreads();
#pragma unroll
    for (int i = 0; i < 4; i++) {
        const int n = n0 + ty + i * 8, k = k0 + tx;
        T[(size_t)n * KGLOB + k] = __float2half(tile[tx][ty + i * 8]);
    }
}

// ---------------- reductions ----------------
__device__ __forceinline__ float warpSum(float v) {
#pragma unroll
    for (int o = 16; o > 0; o >>= 1) v += __shfl_down_sync(0xffffffffu, v, o);
    return v;
}
__device__ __forceinline__ float blockSum(float v, float* sm, int nwarps) {
    int lane = threadIdx.x & 31, w = threadIdx.x >> 5;
    v = warpSum(v);
    __syncthreads();
    if (lane == 0) sm[w] = v;
    __syncthreads();
    if (w == 0) {
        float x = (lane < nwarps) ? sm[lane] : 0.f;
        x = warpSum(x);
        if (lane == 0) sm[0] = x;
    }
    __syncthreads();
    return sm[0];
}

// ---------------- LayerNorm in place on fp16 buffer ----------------
__global__ void layernorm_inplace_kernel(__half2* __restrict__ h, const float* __restrict__ g,
                                         const float* __restrict__ beta)
{
    __shared__ float sred[8];
    const int row = blockIdx.x;
    __half2* r = h + (size_t)row * (H_ / 2);
    const int t2 = threadIdx.x * 2;
    __half2 a = r[t2], b = r[t2 + 1];
    float2 fa = __half22float2(a), fb = __half22float2(b);
    float s = fa.x + fa.y + fb.x + fb.y;
    s = blockSum(s, sred, 8);
    const float mu = s * (1.0f / H_);
    const float dx = fa.x - mu, dy = fa.y - mu, dz = fb.x - mu, dw = fb.y - mu;
    float q = dx * dx + dy * dy + dz * dz + dw * dw;
    q = blockSum(q, sred, 8);
    const float rsig = rsqrtf(q * (1.0f / H_) + 1e-5f);
    const int c = threadIdx.x * 4;
    const float ox = dx * rsig * g[c + 0] + beta[c + 0];
    const float oy = dy * rsig * g[c + 1] + beta[c + 1];
    const float oz = dz * rsig * g[c + 2] + beta[c + 2];
    const float ow = dw * rsig * g[c + 3] + beta[c + 3];
    r[t2]     = __halves2half2(__float2half(ox), __float2half(oy));
    r[t2 + 1] = __halves2half2(__float2half(oz), __float2half(ow));
}

// ---------------- evidential head (reads split-K partials, adds bias) ----------------
__device__ __forceinline__ float softplusf(float x) {
    return fmaxf(x, 0.f) + log1pf(__expf(-fabsf(x)));
}
__device__ __forceinline__ float digammaf_(float x) {
    float r = 0.f;
#pragma unroll
    for (int i = 0; i < 5; i++) {
        if (x < 6.f) { r -= __fdividef(1.f, x); x += 1.f; }
    }
    const float inv = __fdividef(1.f, x);
    const float inv2 = inv * inv;
    const float ser = inv2 * (0.0833333333f - inv2 * (0.0083333333f - inv2 * 0.0039682540f));
    return r + logf(x) - 0.5f * inv - ser;
}

__global__ void head_kernel(const float* __restrict__ partial, const float* __restrict__ b3,
                            float* __restrict__ alpha_o, float* __restrict__ evid_o,
                            float* __restrict__ eprob_o, float* __restrict__ vac_o,
                            float* __restrict__ diss_o, float* __restrict__ alea_o)
{
    __shared__ float sb[K_];
    __shared__ float sa[K_];
    __shared__ float sm[4];
    const int row = blockIdx.x;
    const int t = threadIdx.x;

    float e = 0.f, a = 0.f;
    if (t < K_) {
        float xv = b3[t];
        const float* pp = partial + (size_t)row * 128 + t;
#pragma unroll
        for (int c = 0; c < SPLITK; c++) xv += pp[c * PSTRIDE];
        e = softplusf(xv);
        a = e + 1.f;
    }
    const float S = blockSum(a, sm, 4);

    if (t < K_) {
        const size_t o = (size_t)row * K_ + t;
        alpha_o[o] = a;
        evid_o[o] = e;
        eprob_o[o] = a / S;
        sb[t] = e / S;
        sa[t] = a;
    }
    if (t == 0) vac_o[row] = (float)K_ / S;
    __syncthreads();

    float pairsum = 0.f;
    for (int idx = t; idx < K_ * K_; idx += 128) {
        const int i = idx / K_;
        const int j = idx - i * K_;
        if (i < j) {
            const float bi = sb[i], bj = sb[j];
            const float den = bi + bj + 1e-8f;
            pairsum += (1.f - __fdividef(fabsf(bi - bj), den)) * bi * bj;
        }
    }
    pairsum = blockSum(pairsum, sm, 4);

    const float psiS = digammaf_(S);
    float al = 0.f;
    if (t < K_) al = (sa[t] / S) * (digammaf_(sa[t]) - psiS);
    const float alea = blockSum(al, sm, 4);

    if (t == 0) {
        diss_o[row] = pairsum;
        alea_o[row] = -alea;
    }
}

// ---------------- launch ----------------
extern "C" void kernel_launch(void* const* d_in, const int* in_sizes, int n_in,
                              void* d_out, int out_size)
{
    const float* x    = (const float*)d_in[0];
    const float* W1   = (const float*)d_in[1];
    const float* b1   = (const float*)d_in[2];
    const float* g    = (const float*)d_in[3];
    const float* beta = (const float*)d_in[4];
    const float* W2   = (const float*)d_in[5];
    const float* b2   = (const float*)d_in[6];
    const float* W3   = (const float*)d_in[7];
    const float* b3   = (const float*)d_in[8];

    void *p;
    cudaGetSymbolAddress(&p, g_xhi);  __half* xhi  = (__half*)p;
    cudaGetSymbolAddress(&p, g_h1hi); __half* h1hi = (__half*)p;
    cudaGetSymbolAddress(&p, g_h2hi); __half* h2hi = (__half*)p;
    cudaGetSymbolAddress(&p, g_w1hi); __half* w1hi = (__half*)p;
    cudaGetSymbolAddress(&p, g_w2hi); __half* w2hi = (__half*)p;
    cudaGetSymbolAddress(&p, g_w3hi); __half* w3hi = (__half*)p;
    cudaGetSymbolAddress(&p, g_part); float* part = (float*)p;

    const int DSMEM = NSTG * (int)STGB;   // 110592
    cudaFuncSetAttribute(gemm_mma, cudaFuncAttributeMaxDynamicSharedMemorySize, DSMEM);

    const int splitBlocks = (B_ * H_) / 4 / 256;   // 8192

    // weight prep (transposed fp16)
    transpose_hi<<<dim3(32, 32), dim3(32, 8)>>>(W1, w1hi, H_);
    transpose_hi<<<dim3(32, 32), dim3(32, 8)>>>(W2, w2hi, H_);
    transpose_hi<<<dim3(4, 32),  dim3(32, 8)>>>(W3, w3hi, K_);

    // x -> fp16
    split_kernel<<<splitBlocks, 256>>>((const float4*)x, (__half2*)xhi);

    // GEMM1 + silu -> fp16 h1 (direct)
    gemm_mma<<<dim3(8, 64, 1), 256, DSMEM>>>(xhi, w1hi, b1, nullptr, h1hi, H_, 1, 1, 16, 0);
    // LayerNorm in place on fp16 h1
    layernorm_inplace_kernel<<<B_, 256>>>((__half2*)h1hi, g, beta);
    // GEMM2 + silu -> fp16 h2
    gemm_mma<<<dim3(8, 64, 1), 256, DSMEM>>>(h1hi, w2hi, b2, nullptr, h2hi, H_, 1, 1, 16, 0);
    // GEMM3 split-K=8 -> fp32 partials
    gemm_mma<<<dim3(1, 64, SPLITK), 256, DSMEM>>>(h2hi, w3hi, nullptr, part, nullptr,
                                                  128, 0, 0, 16 / SPLITK, PSTRIDE);

    float* out = (float*)d_out;
    const size_t BK = (size_t)B_ * K_;
    head_kernel<<<B_, 128>>>(part, b3,
                             out,                    // alpha
                             out + BK,               // evidence
                             out + 2 * BK,           // expected_prob
                             out + 3 * BK,           // vacuity
                             out + 3 * BK + B_,      // dissonance
                             out + 3 * BK + 2 * B_); // aleatoric
}